// round 5
// baseline (speedup 1.0000x reference)
#include <cuda_runtime.h>
#include <math.h>

// ---------------- scratch (device globals; no allocation allowed) ----------
// t,p,g stacked: [n][which*256 + a][l], which in {0=theta,1=phi,2=g}
__device__ float g_tpg[3ull * 16 * 256 * 1024];     // 48 MB
__device__ float g_attn[16ull * 256 * 1024];        // 16 MB
__device__ float g_partm[16 * 64];
__device__ float g_parts[16 * 64];
__device__ float g_M[16];
__device__ float g_invZ[16];

#define LDIM 1024
#define CDIM 256
#define NB   16

// =====================================================================
// K1: fused theta/phi/g : out[m][l] = sum_k Wsel[a][k] * x[n][k][l]
//   M=768 (3*256), N=1024, K=256.  128x128x8 tile, 8x8 per thread.
// =====================================================================
__global__ __launch_bounds__(256) void k_tpg(const float* __restrict__ x,
                                             const float* __restrict__ wt,
                                             const float* __restrict__ wp,
                                             const float* __restrict__ wg) {
    __shared__ float As[8][128];
    __shared__ float Bs[8][128];
    const int n  = blockIdx.z;
    const int m0 = blockIdx.y * 128;
    const int l0 = blockIdx.x * 128;
    const float* xn = x + (size_t)n * CDIM * LDIM;

    const int tid  = threadIdx.x;
    const int row0 = (tid >> 4) * 8;
    const int col0 = (tid & 15) * 8;
    const int am  = tid >> 1, ak4 = (tid & 1) * 4;   // A: transpose-load
    const int bk  = tid >> 5, bn4 = (tid & 31) * 4;  // B: direct float4

    const int m = m0 + am;
    const float* wsel = (m < 256) ? wt : ((m < 512) ? wp : wg);
    const int a = m & 255;

    float acc[8][8];
#pragma unroll
    for (int r = 0; r < 8; r++)
#pragma unroll
        for (int c = 0; c < 8; c++) acc[r][c] = 0.f;

    for (int k0 = 0; k0 < CDIM; k0 += 8) {
        float4 av = *(const float4*)(wsel + a * CDIM + k0 + ak4);
        As[ak4 + 0][am] = av.x; As[ak4 + 1][am] = av.y;
        As[ak4 + 2][am] = av.z; As[ak4 + 3][am] = av.w;
        *(float4*)&Bs[bk][bn4] = *(const float4*)(xn + (size_t)(k0 + bk) * LDIM + l0 + bn4);
        __syncthreads();
#pragma unroll
        for (int k = 0; k < 8; k++) {
            float a8[8], b8[8];
            *(float4*)a8       = *(float4*)&As[k][row0];
            *(float4*)(a8 + 4) = *(float4*)&As[k][row0 + 4];
            *(float4*)b8       = *(float4*)&Bs[k][col0];
            *(float4*)(b8 + 4) = *(float4*)&Bs[k][col0 + 4];
#pragma unroll
            for (int r = 0; r < 8; r++)
#pragma unroll
                for (int c = 0; c < 8; c++) acc[r][c] = fmaf(a8[r], b8[c], acc[r][c]);
        }
        __syncthreads();
    }
    float* out = g_tpg + ((size_t)n * 768) * LDIM;
#pragma unroll
    for (int r = 0; r < 8; r++) {
        float* o = out + (size_t)(m0 + row0 + r) * LDIM + l0 + col0;
        *(float4*)o       = *(float4*)&acc[r][0];
        *(float4*)(o + 4) = *(float4*)&acc[r][4];
    }
}

// =====================================================================
// K2: c[n][i][j] = sum_a t[n][a][i] * p[n][a][j]   (A = t^T is K-major)
//   M=N=1024, K=256.
// =====================================================================
__global__ __launch_bounds__(256) void k_c(float* __restrict__ cout) {
    __shared__ float As[8][128];
    __shared__ float Bs[8][128];
    const int n  = blockIdx.z;
    const int i0 = blockIdx.y * 128;
    const int j0 = blockIdx.x * 128;
    const float* t = g_tpg + ((size_t)n * 768 + 0)   * LDIM;
    const float* p = g_tpg + ((size_t)n * 768 + 256) * LDIM;

    const int tid  = threadIdx.x;
    const int row0 = (tid >> 4) * 8;
    const int col0 = (tid & 15) * 8;
    const int ak  = tid >> 5, am4 = (tid & 31) * 4;  // A K-major: direct float4
    const int bk  = ak,       bn4 = am4;

    float acc[8][8];
#pragma unroll
    for (int r = 0; r < 8; r++)
#pragma unroll
        for (int c = 0; c < 8; c++) acc[r][c] = 0.f;

    for (int k0 = 0; k0 < CDIM; k0 += 8) {
        *(float4*)&As[ak][am4] = *(const float4*)(t + (size_t)(k0 + ak) * LDIM + i0 + am4);
        *(float4*)&Bs[bk][bn4] = *(const float4*)(p + (size_t)(k0 + bk) * LDIM + j0 + bn4);
        __syncthreads();
#pragma unroll
        for (int k = 0; k < 8; k++) {
            float a8[8], b8[8];
            *(float4*)a8       = *(float4*)&As[k][row0];
            *(float4*)(a8 + 4) = *(float4*)&As[k][row0 + 4];
            *(float4*)b8       = *(float4*)&Bs[k][col0];
            *(float4*)(b8 + 4) = *(float4*)&Bs[k][col0 + 4];
#pragma unroll
            for (int r = 0; r < 8; r++)
#pragma unroll
                for (int c = 0; c < 8; c++) acc[r][c] = fmaf(a8[r], b8[c], acc[r][c]);
        }
        __syncthreads();
    }
    float* out = cout + (size_t)n * LDIM * LDIM;
#pragma unroll
    for (int r = 0; r < 8; r++) {
        float* o = out + (size_t)(i0 + row0 + r) * LDIM + j0 + col0;
        *(float4*)o       = *(float4*)&acc[r][0];
        *(float4*)(o + 4) = *(float4*)&acc[r][4];
    }
}

// =====================================================================
// K3a: per (n, blk) partial max + partial sum(exp(v - local_max)) over 16384 elems
// =====================================================================
__global__ __launch_bounds__(256) void k_sm_partial(const float* __restrict__ cin) {
    __shared__ float red[256];
    const int n = blockIdx.y, blk = blockIdx.x, tid = threadIdx.x;
    const float4* base = (const float4*)(cin + (size_t)n * LDIM * LDIM + (size_t)blk * 16384);

    float m = -1e30f;
#pragma unroll
    for (int it = 0; it < 16; it++) {
        float4 v = base[it * 256 + tid];
        m = fmaxf(m, fmaxf(fmaxf(v.x, v.y), fmaxf(v.z, v.w)));
    }
    red[tid] = m;
    __syncthreads();
    for (int s = 128; s > 0; s >>= 1) {
        if (tid < s) red[tid] = fmaxf(red[tid], red[tid + s]);
        __syncthreads();
    }
    const float bm = red[0];
    __syncthreads();

    float sum = 0.f;
#pragma unroll
    for (int it = 0; it < 16; it++) {
        float4 v = base[it * 256 + tid];
        sum += expf(v.x - bm) + expf(v.y - bm) + expf(v.z - bm) + expf(v.w - bm);
    }
    red[tid] = sum;
    __syncthreads();
    for (int s = 128; s > 0; s >>= 1) {
        if (tid < s) red[tid] += red[tid + s];
        __syncthreads();
    }
    if (tid == 0) {
        g_partm[n * 64 + blk] = bm;
        g_parts[n * 64 + blk] = red[0];
    }
}

// K3b: combine 64 partials per n -> global M, 1/Z
__global__ __launch_bounds__(64) void k_sm_final() {
    __shared__ float rm[64];
    __shared__ float rs[64];
    const int n = blockIdx.x, tid = threadIdx.x;
    float m = g_partm[n * 64 + tid];
    rm[tid] = m;
    __syncthreads();
    for (int s = 32; s > 0; s >>= 1) {
        if (tid < s) rm[tid] = fmaxf(rm[tid], rm[tid + s]);
        __syncthreads();
    }
    const float M = rm[0];
    __syncthreads();
    rs[tid] = g_parts[n * 64 + tid] * expf(m - M);
    __syncthreads();
    for (int s = 32; s > 0; s >>= 1) {
        if (tid < s) rs[tid] += rs[tid + s];
        __syncthreads();
    }
    if (tid == 0) { g_M[n] = M; g_invZ[n] = 1.f / rs[0]; }
}

// =====================================================================
// K4: attn[n][a][j] = invZ * sum_i g[n][a][i] * exp(c[n][i][j] - M)
//   M=256, N=1024, K=1024. exp fused into B-tile load.
// =====================================================================
__global__ __launch_bounds__(256) void k_attn(const float* __restrict__ cin) {
    __shared__ float As[8][128];
    __shared__ float Bs[8][128];
    const int n  = blockIdx.z;
    const int m0 = blockIdx.y * 128;
    const int j0 = blockIdx.x * 128;
    const float* gmat = g_tpg + ((size_t)n * 768 + 512) * LDIM;
    const float* cn   = cin + (size_t)n * LDIM * LDIM;
    const float  M    = g_M[n];
    const float  invZ = g_invZ[n];

    const int tid  = threadIdx.x;
    const int row0 = (tid >> 4) * 8;
    const int col0 = (tid & 15) * 8;
    const int am  = tid >> 1, ak4 = (tid & 1) * 4;
    const int bk  = tid >> 5, bn4 = (tid & 31) * 4;

    float acc[8][8];
#pragma unroll
    for (int r = 0; r < 8; r++)
#pragma unroll
        for (int c = 0; c < 8; c++) acc[r][c] = 0.f;

    for (int k0 = 0; k0 < LDIM; k0 += 8) {
        float4 av = *(const float4*)(gmat + (size_t)(m0 + am) * LDIM + k0 + ak4);
        As[ak4 + 0][am] = av.x; As[ak4 + 1][am] = av.y;
        As[ak4 + 2][am] = av.z; As[ak4 + 3][am] = av.w;
        float4 bv = *(const float4*)(cn + (size_t)(k0 + bk) * LDIM + j0 + bn4);
        bv.x = expf(bv.x - M); bv.y = expf(bv.y - M);
        bv.z = expf(bv.z - M); bv.w = expf(bv.w - M);
        *(float4*)&Bs[bk][bn4] = bv;
        __syncthreads();
#pragma unroll
        for (int k = 0; k < 8; k++) {
            float a8[8], b8[8];
            *(float4*)a8       = *(float4*)&As[k][row0];
            *(float4*)(a8 + 4) = *(float4*)&As[k][row0 + 4];
            *(float4*)b8       = *(float4*)&Bs[k][col0];
            *(float4*)(b8 + 4) = *(float4*)&Bs[k][col0 + 4];
#pragma unroll
            for (int r = 0; r < 8; r++)
#pragma unroll
                for (int c = 0; c < 8; c++) acc[r][c] = fmaf(a8[r], b8[c], acc[r][c]);
        }
        __syncthreads();
    }
    float* out = g_attn + (size_t)n * CDIM * LDIM;
#pragma unroll
    for (int r = 0; r < 8; r++) {
        float* o = out + (size_t)(m0 + row0 + r) * LDIM + j0 + col0;
#pragma unroll
        for (int c = 0; c < 8; c++) o[c] = acc[r][c] * invZ;
    }
}

// =====================================================================
// K5: y[n][c][j] = x[n][c][j] + sum_a w_restore[c][a] * attn[n][a][j]
//   M=256, N=1024, K=256.
// =====================================================================
__global__ __launch_bounds__(256) void k_out(const float* __restrict__ wr,
                                             const float* __restrict__ x,
                                             float* __restrict__ y) {
    __shared__ float As[8][128];
    __shared__ float Bs[8][128];
    const int n  = blockIdx.z;
    const int m0 = blockIdx.y * 128;
    const int j0 = blockIdx.x * 128;
    const float* an = g_attn + (size_t)n * CDIM * LDIM;
    const float* xn = x + (size_t)n * CDIM * LDIM;

    const int tid  = threadIdx.x;
    const int row0 = (tid >> 4) * 8;
    const int col0 = (tid & 15) * 8;
    const int am  = tid >> 1, ak4 = (tid & 1) * 4;
    const int bk  = tid >> 5, bn4 = (tid & 31) * 4;

    float acc[8][8];
#pragma unroll
    for (int r = 0; r < 8; r++)
#pragma unroll
        for (int c = 0; c < 8; c++) acc[r][c] = 0.f;

    for (int k0 = 0; k0 < CDIM; k0 += 8) {
        float4 av = *(const float4*)(wr + (size_t)(m0 + am) * CDIM + k0 + ak4);
        As[ak4 + 0][am] = av.x; As[ak4 + 1][am] = av.y;
        As[ak4 + 2][am] = av.z; As[ak4 + 3][am] = av.w;
        *(float4*)&Bs[bk][bn4] = *(const float4*)(an + (size_t)(k0 + bk) * LDIM + j0 + bn4);
        __syncthreads();
#pragma unroll
        for (int k = 0; k < 8; k++) {
            float a8[8], b8[8];
            *(float4*)a8       = *(float4*)&As[k][row0];
            *(float4*)(a8 + 4) = *(float4*)&As[k][row0 + 4];
            *(float4*)b8       = *(float4*)&Bs[k][col0];
            *(float4*)(b8 + 4) = *(float4*)&Bs[k][col0 + 4];
#pragma unroll
            for (int r = 0; r < 8; r++)
#pragma unroll
                for (int c = 0; c < 8; c++) acc[r][c] = fmaf(a8[r], b8[c], acc[r][c]);
        }
        __syncthreads();
    }
    float* yn = y + (size_t)n * CDIM * LDIM;
#pragma unroll
    for (int r = 0; r < 8; r++) {
        const int row = m0 + row0 + r;
        float* o = yn + (size_t)row * LDIM + j0 + col0;
        const float* xi = xn + (size_t)row * LDIM + j0 + col0;
#pragma unroll
        for (int c = 0; c < 8; c++) o[c] = acc[r][c] + xi[c];
    }
}

// =====================================================================
extern "C" void kernel_launch(void* const* d_in, const int* in_sizes, int n_in,
                              void* d_out, int out_size) {
    const float* x  = (const float*)d_in[0];
    const float* wt = (const float*)d_in[1];
    const float* wp = (const float*)d_in[2];
    const float* wg = (const float*)d_in[3];
    const float* wr = (const float*)d_in[4];
    float* out = (float*)d_out;
    float* c_out = out;                                   // [16,1024,1024]
    float* y_out = out + (size_t)NB * LDIM * LDIM;        // [16,256,32,32]

    // K1: t,p,g
    k_tpg<<<dim3(LDIM / 128, 768 / 128, NB), 256>>>(x, wt, wp, wg);
    // K2: c = t^T p
    k_c<<<dim3(LDIM / 128, LDIM / 128, NB), 256>>>(c_out);
    // K3: global softmax stats
    k_sm_partial<<<dim3(64, NB), 256>>>(c_out);
    k_sm_final<<<NB, 64>>>();
    // K4: attn = (1/Z) g @ exp(c - M)
    k_attn<<<dim3(LDIM / 128, CDIM / 128, NB), 256>>>(c_out);
    // K5: y = x + wr @ attn
    k_out<<<dim3(LDIM / 128, CDIM / 128, NB), 256>>>(wr, x, y_out);
}

// round 6
// speedup vs baseline: 1.0807x; 1.0807x over previous
#include <cuda_runtime.h>
#include <math.h>

typedef unsigned long long u64;

// ---------------- scratch (device globals; no allocation allowed) ----------
__device__ float g_tpg[3ull * 16 * 256 * 1024];     // t,p,g [n][which*256+a][l]
__device__ float g_attn[16ull * 256 * 1024];
__device__ float g_partm[16 * 64];
__device__ float g_parts[16 * 64];
__device__ float g_M[16];
__device__ float g_invZ[16];

#define LDIM 1024
#define CDIM 256
#define NB   16

// ---------------- packed f32x2 helpers ----------------
__device__ __forceinline__ u64 bc2(float a) {
    u64 r;
    asm("mov.b64 %0, {%1, %1};" : "=l"(r) : "f"(a));
    return r;
}
__device__ __forceinline__ void fma2(u64& d, u64 a, u64 b) {
    asm("fma.rn.f32x2 %0, %1, %2, %0;" : "+l"(d) : "l"(a), "l"(b));
}
__device__ __forceinline__ float2 unpk(u64 v) {
    float lo, hi;
    asm("mov.b64 {%0, %1}, %2;" : "=f"(lo), "=f"(hi) : "l"(v));
    return make_float2(lo, hi);
}
__device__ __forceinline__ float4 pair4(u64 a, u64 b) {
    float2 x = unpk(a), y = unpk(b);
    return make_float4(x.x, x.y, y.x, y.y);
}

// Inner product step shared by all GEMMs: 8 rows x 8 cols (4 f32x2 pairs)
#define FFMA2_STEP(As_, Bs_, k_)                                               \
    do {                                                                       \
        float a8[8];                                                           \
        *(float4*)a8       = *(const float4*)&As_[k_][row0];                   \
        *(float4*)(a8 + 4) = *(const float4*)&As_[k_][row0 + 4];               \
        ulonglong2 bA = *(const ulonglong2*)&Bs_[k_][col0];                    \
        ulonglong2 bB = *(const ulonglong2*)&Bs_[k_][col0 + 4];                \
        u64 ap[8];                                                             \
        _Pragma("unroll") for (int r = 0; r < 8; r++) ap[r] = bc2(a8[r]);      \
        _Pragma("unroll") for (int r = 0; r < 8; r++) {                        \
            fma2(acc2[r][0], ap[r], bA.x);                                     \
            fma2(acc2[r][1], ap[r], bA.y);                                     \
            fma2(acc2[r][2], ap[r], bB.x);                                     \
            fma2(acc2[r][3], ap[r], bB.y);                                     \
        }                                                                      \
    } while (0)

#define ACC_INIT()                                                             \
    u64 acc2[8][4];                                                            \
    _Pragma("unroll") for (int r = 0; r < 8; r++)                              \
        _Pragma("unroll") for (int c = 0; c < 4; c++) acc2[r][c] = 0ull;

// =====================================================================
// K1: fused theta/phi/g : out[m][l] = sum_k Wsel[a][k] * x[n][k][l]
//   M=768 (3*256), N=1024, K=256.  128x128x8 tile, 8x8 per thread.
// =====================================================================
__global__ __launch_bounds__(256) void k_tpg(const float* __restrict__ x,
                                             const float* __restrict__ wt,
                                             const float* __restrict__ wp,
                                             const float* __restrict__ wg) {
    __shared__ __align__(16) float As[8][128];
    __shared__ __align__(16) float Bs[8][128];
    const int n  = blockIdx.z;
    const int m0 = blockIdx.y * 128;
    const int l0 = blockIdx.x * 128;
    const float* xn = x + (size_t)n * CDIM * LDIM;

    const int tid  = threadIdx.x;
    const int row0 = (tid >> 4) * 8;
    const int col0 = (tid & 15) * 8;
    const int am  = tid >> 1, ak4 = (tid & 1) * 4;   // A: transpose-load
    const int bk  = tid >> 5, bn4 = (tid & 31) * 4;  // B: direct float4

    const int m = m0 + am;
    const float* wsel = (m < 256) ? wt : ((m < 512) ? wp : wg);
    const int a = m & 255;

    ACC_INIT();

    for (int k0 = 0; k0 < CDIM; k0 += 8) {
        float4 av = *(const float4*)(wsel + a * CDIM + k0 + ak4);
        As[ak4 + 0][am] = av.x; As[ak4 + 1][am] = av.y;
        As[ak4 + 2][am] = av.z; As[ak4 + 3][am] = av.w;
        *(float4*)&Bs[bk][bn4] = *(const float4*)(xn + (size_t)(k0 + bk) * LDIM + l0 + bn4);
        __syncthreads();
#pragma unroll
        for (int k = 0; k < 8; k++) FFMA2_STEP(As, Bs, k);
        __syncthreads();
    }
    float* out = g_tpg + ((size_t)n * 768) * LDIM;
#pragma unroll
    for (int r = 0; r < 8; r++) {
        float* o = out + (size_t)(m0 + row0 + r) * LDIM + l0 + col0;
        *(float4*)o       = pair4(acc2[r][0], acc2[r][1]);
        *(float4*)(o + 4) = pair4(acc2[r][2], acc2[r][3]);
    }
}

// =====================================================================
// K2: c[n][i][j] = sum_a t[n][a][i] * p[n][a][j]   (A = t^T is K-major)
//   M=N=1024, K=256.
// =====================================================================
__global__ __launch_bounds__(256) void k_c(float* __restrict__ cout) {
    __shared__ __align__(16) float As[8][128];
    __shared__ __align__(16) float Bs[8][128];
    const int n  = blockIdx.z;
    const int i0 = blockIdx.y * 128;
    const int j0 = blockIdx.x * 128;
    const float* t = g_tpg + ((size_t)n * 768 + 0)   * LDIM;
    const float* p = g_tpg + ((size_t)n * 768 + 256) * LDIM;

    const int tid  = threadIdx.x;
    const int row0 = (tid >> 4) * 8;
    const int col0 = (tid & 15) * 8;
    const int ak  = tid >> 5, am4 = (tid & 31) * 4;  // direct float4 loads
    const int bk  = ak,       bn4 = am4;

    ACC_INIT();

    for (int k0 = 0; k0 < CDIM; k0 += 8) {
        *(float4*)&As[ak][am4] = *(const float4*)(t + (size_t)(k0 + ak) * LDIM + i0 + am4);
        *(float4*)&Bs[bk][bn4] = *(const float4*)(p + (size_t)(k0 + bk) * LDIM + j0 + bn4);
        __syncthreads();
#pragma unroll
        for (int k = 0; k < 8; k++) FFMA2_STEP(As, Bs, k);
        __syncthreads();
    }
    float* out = cout + (size_t)n * LDIM * LDIM;
#pragma unroll
    for (int r = 0; r < 8; r++) {
        float* o = out + (size_t)(i0 + row0 + r) * LDIM + j0 + col0;
        *(float4*)o       = pair4(acc2[r][0], acc2[r][1]);
        *(float4*)(o + 4) = pair4(acc2[r][2], acc2[r][3]);
    }
}

// =====================================================================
// K3a: single-pass online (max, sum-exp) partials per (n, blk) over 16384 elems
// =====================================================================
__global__ __launch_bounds__(256) void k_sm_partial(const float* __restrict__ cin) {
    __shared__ float rm[256];
    __shared__ float rs[256];
    const int n = blockIdx.y, blk = blockIdx.x, tid = threadIdx.x;
    const float4* base = (const float4*)(cin + (size_t)n * LDIM * LDIM + (size_t)blk * 16384);

    float m = -1e30f, s = 0.f;
#pragma unroll
    for (int it = 0; it < 16; it++) {
        float4 v = base[it * 256 + tid];
        float vm = fmaxf(fmaxf(v.x, v.y), fmaxf(v.z, v.w));
        if (vm > m) { s *= __expf(m - vm); m = vm; }
        s += __expf(v.x - m) + __expf(v.y - m) + __expf(v.z - m) + __expf(v.w - m);
    }
    rm[tid] = m; rs[tid] = s;
    __syncthreads();
    for (int str = 128; str > 0; str >>= 1) {
        if (tid < str) {
            float m2 = rm[tid + str], s2 = rs[tid + str];
            float M = fmaxf(rm[tid], m2);
            rs[tid] = rs[tid] * __expf(rm[tid] - M) + s2 * __expf(m2 - M);
            rm[tid] = M;
        }
        __syncthreads();
    }
    if (tid == 0) {
        g_partm[n * 64 + blk] = rm[0];
        g_parts[n * 64 + blk] = rs[0];
    }
}

// K3b: combine 64 partials per n -> global M, 1/Z
__global__ __launch_bounds__(64) void k_sm_final() {
    __shared__ float rm[64];
    __shared__ float rs[64];
    const int n = blockIdx.x, tid = threadIdx.x;
    float m = g_partm[n * 64 + tid];
    rm[tid] = m;
    __syncthreads();
    for (int s = 32; s > 0; s >>= 1) {
        if (tid < s) rm[tid] = fmaxf(rm[tid], rm[tid + s]);
        __syncthreads();
    }
    const float M = rm[0];
    __syncthreads();
    rs[tid] = g_parts[n * 64 + tid] * __expf(m - M);
    __syncthreads();
    for (int s = 32; s > 0; s >>= 1) {
        if (tid < s) rs[tid] += rs[tid + s];
        __syncthreads();
    }
    if (tid == 0) { g_M[n] = M; g_invZ[n] = 1.f / rs[0]; }
}

// =====================================================================
// K4: attn[n][a][j] = invZ * sum_i g[n][a][i] * exp(c[n][i][j] - M)
//   M=256, N=1024, K=1024. exp fused into B-tile load.
// =====================================================================
__global__ __launch_bounds__(256) void k_attn(const float* __restrict__ cin) {
    __shared__ __align__(16) float As[8][128];
    __shared__ __align__(16) float Bs[8][128];
    const int n  = blockIdx.z;
    const int m0 = blockIdx.y * 128;
    const int j0 = blockIdx.x * 128;
    const float* gmat = g_tpg + ((size_t)n * 768 + 512) * LDIM;
    const float* cn   = cin + (size_t)n * LDIM * LDIM;
    const float  M    = g_M[n];
    const float  invZ = g_invZ[n];

    const int tid  = threadIdx.x;
    const int row0 = (tid >> 4) * 8;
    const int col0 = (tid & 15) * 8;
    const int am  = tid >> 1, ak4 = (tid & 1) * 4;
    const int bk  = tid >> 5, bn4 = (tid & 31) * 4;

    ACC_INIT();

    for (int k0 = 0; k0 < LDIM; k0 += 8) {
        float4 av = *(const float4*)(gmat + (size_t)(m0 + am) * LDIM + k0 + ak4);
        As[ak4 + 0][am] = av.x; As[ak4 + 1][am] = av.y;
        As[ak4 + 2][am] = av.z; As[ak4 + 3][am] = av.w;
        float4 bv = *(const float4*)(cn + (size_t)(k0 + bk) * LDIM + j0 + bn4);
        bv.x = __expf(bv.x - M); bv.y = __expf(bv.y - M);
        bv.z = __expf(bv.z - M); bv.w = __expf(bv.w - M);
        *(float4*)&Bs[bk][bn4] = bv;
        __syncthreads();
#pragma unroll
        for (int k = 0; k < 8; k++) FFMA2_STEP(As, Bs, k);
        __syncthreads();
    }
    float* out = g_attn + (size_t)n * CDIM * LDIM;
#pragma unroll
    for (int r = 0; r < 8; r++) {
        float* o = out + (size_t)(m0 + row0 + r) * LDIM + j0 + col0;
        float4 o0 = pair4(acc2[r][0], acc2[r][1]);
        float4 o1 = pair4(acc2[r][2], acc2[r][3]);
        o0.x *= invZ; o0.y *= invZ; o0.z *= invZ; o0.w *= invZ;
        o1.x *= invZ; o1.y *= invZ; o1.z *= invZ; o1.w *= invZ;
        *(float4*)o       = o0;
        *(float4*)(o + 4) = o1;
    }
}

// =====================================================================
// K5: y[n][c][j] = x[n][c][j] + sum_a w_restore[c][a] * attn[n][a][j]
//   M=256, N=1024, K=256.
// =====================================================================
__global__ __launch_bounds__(256) void k_out(const float* __restrict__ wr,
                                             const float* __restrict__ x,
                                             float* __restrict__ y) {
    __shared__ __align__(16) float As[8][128];
    __shared__ __align__(16) float Bs[8][128];
    const int n  = blockIdx.z;
    const int m0 = blockIdx.y * 128;
    const int j0 = blockIdx.x * 128;
    const float* an = g_attn + (size_t)n * CDIM * LDIM;
    const float* xn = x + (size_t)n * CDIM * LDIM;

    const int tid  = threadIdx.x;
    const int row0 = (tid >> 4) * 8;
    const int col0 = (tid & 15) * 8;
    const int am  = tid >> 1, ak4 = (tid & 1) * 4;
    const int bk  = tid >> 5, bn4 = (tid & 31) * 4;

    ACC_INIT();

    for (int k0 = 0; k0 < CDIM; k0 += 8) {
        float4 av = *(const float4*)(wr + (size_t)(m0 + am) * CDIM + k0 + ak4);
        As[ak4 + 0][am] = av.x; As[ak4 + 1][am] = av.y;
        As[ak4 + 2][am] = av.z; As[ak4 + 3][am] = av.w;
        *(float4*)&Bs[bk][bn4] = *(const float4*)(an + (size_t)(k0 + bk) * LDIM + j0 + bn4);
        __syncthreads();
#pragma unroll
        for (int k = 0; k < 8; k++) FFMA2_STEP(As, Bs, k);
        __syncthreads();
    }
    float* yn = y + (size_t)n * CDIM * LDIM;
#pragma unroll
    for (int r = 0; r < 8; r++) {
        const int row = m0 + row0 + r;
        float* o = yn + (size_t)row * LDIM + j0 + col0;
        const float* xi = xn + (size_t)row * LDIM + j0 + col0;
        float4 x0 = *(const float4*)xi;
        float4 x1 = *(const float4*)(xi + 4);
        float4 o0 = pair4(acc2[r][0], acc2[r][1]);
        float4 o1 = pair4(acc2[r][2], acc2[r][3]);
        o0.x += x0.x; o0.y += x0.y; o0.z += x0.z; o0.w += x0.w;
        o1.x += x1.x; o1.y += x1.y; o1.z += x1.z; o1.w += x1.w;
        *(float4*)o       = o0;
        *(float4*)(o + 4) = o1;
    }
}

// =====================================================================
extern "C" void kernel_launch(void* const* d_in, const int* in_sizes, int n_in,
                              void* d_out, int out_size) {
    const float* x  = (const float*)d_in[0];
    const float* wt = (const float*)d_in[1];
    const float* wp = (const float*)d_in[2];
    const float* wg = (const float*)d_in[3];
    const float* wr = (const float*)d_in[4];
    float* out = (float*)d_out;
    float* c_out = out;                                   // [16,1024,1024]
    float* y_out = out + (size_t)NB * LDIM * LDIM;        // [16,256,32,32]

    k_tpg<<<dim3(LDIM / 128, 768 / 128, NB), 256>>>(x, wt, wp, wg);
    k_c<<<dim3(LDIM / 128, LDIM / 128, NB), 256>>>(c_out);
    k_sm_partial<<<dim3(64, NB), 256>>>(c_out);
    k_sm_final<<<NB, 64>>>();
    k_attn<<<dim3(LDIM / 128, CDIM / 128, NB), 256>>>(c_out);
    k_out<<<dim3(LDIM / 128, CDIM / 128, NB), 256>>>(wr, x, y_out);
}

// round 11
// speedup vs baseline: 1.5998x; 1.4803x over previous
#include <cuda_runtime.h>
#include <cuda_bf16.h>
#include <stdint.h>
#include <math.h>

#define LDIM 1024
#define CDIM 256
#define NB   16

__device__ float g_tpg[3ull * 16 * 256 * 1024];   // t,p,g [n][which*256+a][l]
__device__ float g_attn[16ull * 256 * 1024];
__device__ float g_partm[16 * 64];
__device__ float g_parts[16 * 64];
__device__ float g_M[16];
__device__ float g_invZ[16];

// ---------------- helpers ----------------
__device__ __forceinline__ uint32_t smem_u32(const void* p) {
    uint32_t a;
    asm("{ .reg .u64 t; cvta.to.shared.u64 t, %1; cvt.u32.u64 %0, t; }" : "=r"(a) : "l"(p));
    return a;
}
__device__ __forceinline__ void hmma(float* c, const uint32_t* a, const uint32_t* b) {
    asm volatile(
        "mma.sync.aligned.m16n8k16.row.col.f32.bf16.bf16.f32 "
        "{%0,%1,%2,%3}, {%4,%5,%6,%7}, {%8,%9}, {%0,%1,%2,%3};"
        : "+f"(c[0]), "+f"(c[1]), "+f"(c[2]), "+f"(c[3])
        : "r"(a[0]), "r"(a[1]), "r"(a[2]), "r"(a[3]), "r"(b[0]), "r"(b[1]));
}
__device__ __forceinline__ void ldsm4(uint32_t* r, uint32_t addr) {
    asm volatile("ldmatrix.sync.aligned.m8n8.x4.shared.b16 {%0,%1,%2,%3}, [%4];"
                 : "=r"(r[0]), "=r"(r[1]), "=r"(r[2]), "=r"(r[3]) : "r"(addr));
}
__device__ __forceinline__ void ldsm4t(uint32_t* r, uint32_t addr) {
    asm volatile("ldmatrix.sync.aligned.m8n8.x4.trans.shared.b16 {%0,%1,%2,%3}, [%4];"
                 : "=r"(r[0]), "=r"(r[1]), "=r"(r[2]), "=r"(r[3]) : "r"(addr));
}
__device__ __forceinline__ uint16_t bfhi(float v) {
    __nv_bfloat16 h = __float2bfloat16(v);
    return reinterpret_cast<uint16_t&>(h);
}
__device__ __forceinline__ uint16_t bflo(float v) {
    float hv = __bfloat162float(__float2bfloat16(v));
    __nv_bfloat16 l = __float2bfloat16(v - hv);
    return reinterpret_cast<uint16_t&>(l);
}

#define AS 40    // A smem row stride (elems): 80B, 16B-multiple, conflict-free
#define BS 136   // B smem row stride (elems): 272B, 16B-multiple, conflict-free

// =====================================================================
// Unified mma.sync GEMM:  D[128 x 128] per block, BK=32, warp tile 64x32.
// MODE: 0=tpg  1=c (A transposed from t)  2=attn (exp fused)  3=y
// =====================================================================
template <int MODE>
__global__ __launch_bounds__(256) void gemm_mma(
    const float* __restrict__ x,  const float* __restrict__ wt,
    const float* __restrict__ wp, const float* __restrict__ wg,
    const float* __restrict__ wr, float* __restrict__ cbuf,
    float* __restrict__ ybuf) {
    __shared__ __align__(16) uint16_t Ah[128][AS], Al[128][AS];
    __shared__ __align__(16) uint16_t Bh[32][BS],  Bl[32][BS];

    const int tid = threadIdx.x;
    const int n = blockIdx.z, j0 = blockIdx.x * 128, m0 = blockIdx.y * 128;
    constexpr int KTOT = (MODE == 2) ? 1024 : 256;

    const float* Asrc; int AK = CDIM;
    const float* Bsrc;
    float eM = 0.f, iZ = 1.f;
    if (MODE == 0) {
        const float* w = (m0 < 256) ? wt : ((m0 < 512) ? wp : wg);
        Asrc = w + (size_t)(m0 & 255) * CDIM;
        Bsrc = x + (size_t)n * CDIM * LDIM;
    } else if (MODE == 1) {
        Asrc = g_tpg + (size_t)n * 768 * LDIM;                  // t [a][i] -> transpose
        Bsrc = g_tpg + ((size_t)n * 768 + 256) * LDIM;          // p [a][j]
    } else if (MODE == 2) {
        Asrc = g_tpg + ((size_t)n * 768 + 512 + m0) * LDIM; AK = LDIM;
        Bsrc = cbuf + (size_t)n * LDIM * LDIM;
        eM = g_M[n]; iZ = g_invZ[n];
    } else {
        Asrc = wr + (size_t)m0 * CDIM;
        Bsrc = g_attn + (size_t)n * CDIM * LDIM;
    }

    const int lane = tid & 31, wid = tid >> 5;
    const int wm = (wid & 1) * 64, wn = (wid >> 1) * 32;
    const int ldrow = lane & 15, ldcol = (lane >> 4) * 8;

    float acc[4][4][4];
#pragma unroll
    for (int a = 0; a < 4; a++)
#pragma unroll
        for (int b = 0; b < 4; b++)
#pragma unroll
            for (int c = 0; c < 4; c++) acc[a][b][c] = 0.f;

    for (int k0 = 0; k0 < KTOT; k0 += 32) {
        __syncthreads();
        // ---- load A tile (128m x 32k) ----
        if (MODE == 1) {
            // t is [a][i]: read along i (coalesced), write transposed
#pragma unroll
            for (int u = 0; u < 4; u++) {
                int idx = tid + 256 * u;
                int a = idx >> 5, i4 = (idx & 31) * 4;
                float4 v = *(const float4*)(Asrc + (size_t)(k0 + a) * LDIM + m0 + i4);
                Ah[i4 + 0][a] = bfhi(v.x); Al[i4 + 0][a] = bflo(v.x);
                Ah[i4 + 1][a] = bfhi(v.y); Al[i4 + 1][a] = bflo(v.y);
                Ah[i4 + 2][a] = bfhi(v.z); Al[i4 + 2][a] = bflo(v.z);
                Ah[i4 + 3][a] = bfhi(v.w); Al[i4 + 3][a] = bflo(v.w);
            }
        } else {
#pragma unroll
            for (int u = 0; u < 4; u++) {
                int idx = tid + 256 * u;
                int m = idx >> 3, k = (idx & 7) * 4;
                float4 v = *(const float4*)(Asrc + (size_t)m * AK + k0 + k);
                Ah[m][k + 0] = bfhi(v.x); Al[m][k + 0] = bflo(v.x);
                Ah[m][k + 1] = bfhi(v.y); Al[m][k + 1] = bflo(v.y);
                Ah[m][k + 2] = bfhi(v.z); Al[m][k + 2] = bflo(v.z);
                Ah[m][k + 3] = bfhi(v.w); Al[m][k + 3] = bflo(v.w);
            }
        }
        // ---- load B tile (32k x 128j), optional exp ----
#pragma unroll
        for (int u = 0; u < 4; u++) {
            int idx = tid + 256 * u;
            int k = idx >> 5, j4 = (idx & 31) * 4;
            float4 v = *(const float4*)(Bsrc + (size_t)(k0 + k) * LDIM + j0 + j4);
            if (MODE == 2) {
                v.x = __expf(v.x - eM); v.y = __expf(v.y - eM);
                v.z = __expf(v.z - eM); v.w = __expf(v.w - eM);
            }
            Bh[k][j4 + 0] = bfhi(v.x); Bl[k][j4 + 0] = bflo(v.x);
            Bh[k][j4 + 1] = bfhi(v.y); Bl[k][j4 + 1] = bflo(v.y);
            Bh[k][j4 + 2] = bfhi(v.z); Bl[k][j4 + 2] = bflo(v.z);
            Bh[k][j4 + 3] = bfhi(v.w); Bl[k][j4 + 3] = bflo(v.w);
        }
        __syncthreads();

        // ---- compute: 2 sub-steps of k16 ----
#pragma unroll
        for (int ks = 0; ks < 32; ks += 16) {
            uint32_t ah[4][4], al[4][4], bhf[4][2], blf[4][2];
#pragma unroll
            for (int mf = 0; mf < 4; mf++) {
                ldsm4(ah[mf], smem_u32(&Ah[wm + mf * 16 + ldrow][ks + ldcol]));
                ldsm4(al[mf], smem_u32(&Al[wm + mf * 16 + ldrow][ks + ldcol]));
            }
#pragma unroll
            for (int nq = 0; nq < 2; nq++) {
                uint32_t r[4];
                ldsm4t(r, smem_u32(&Bh[ks + ldrow][wn + nq * 16 + ldcol]));
                bhf[nq * 2][0] = r[0]; bhf[nq * 2][1] = r[1];
                bhf[nq * 2 + 1][0] = r[2]; bhf[nq * 2 + 1][1] = r[3];
                ldsm4t(r, smem_u32(&Bl[ks + ldrow][wn + nq * 16 + ldcol]));
                blf[nq * 2][0] = r[0]; blf[nq * 2][1] = r[1];
                blf[nq * 2 + 1][0] = r[2]; blf[nq * 2 + 1][1] = r[3];
            }
#pragma unroll
            for (int mf = 0; mf < 4; mf++)
#pragma unroll
                for (int nf = 0; nf < 4; nf++) {
                    hmma(acc[mf][nf], ah[mf], bhf[nf]);
                    hmma(acc[mf][nf], ah[mf], blf[nf]);
                    hmma(acc[mf][nf], al[mf], bhf[nf]);
                }
        }
    }

    // ---- epilogue ----
    const int g = lane >> 2, tg = lane & 3;
    float* obase; const float* xbase = nullptr;
    if (MODE == 0)      obase = g_tpg + ((size_t)n * 768 + m0) * LDIM + j0;
    else if (MODE == 1) obase = cbuf + ((size_t)n * LDIM + m0) * LDIM + j0;
    else if (MODE == 2) obase = g_attn + ((size_t)n * CDIM + m0) * LDIM + j0;
    else {
        obase = ybuf + ((size_t)n * CDIM + m0) * LDIM + j0;
        xbase = x + ((size_t)n * CDIM + m0) * LDIM + j0;
    }
#pragma unroll
    for (int mf = 0; mf < 4; mf++)
#pragma unroll
        for (int nf = 0; nf < 4; nf++) {
            int r0 = wm + mf * 16 + g;
            int cc = wn + nf * 8 + tg * 2;
#pragma unroll
            for (int h = 0; h < 2; h++) {
                int row = r0 + h * 8;
                float2 d = make_float2(acc[mf][nf][h * 2], acc[mf][nf][h * 2 + 1]);
                if (MODE == 2) { d.x *= iZ; d.y *= iZ; }
                if (MODE == 3) {
                    const float2 xv = *(const float2*)(xbase + (size_t)row * LDIM + cc);
                    d.x += xv.x; d.y += xv.y;
                }
                *(float2*)(obase + (size_t)row * LDIM + cc) = d;
            }
        }
}

// ---------------- softmax stats (unchanged) ----------------
__global__ __launch_bounds__(256) void k_sm_partial(const float* __restrict__ cin) {
    __shared__ float rm[256], rs[256];
    const int n = blockIdx.y, blk = blockIdx.x, tid = threadIdx.x;
    const float4* base = (const float4*)(cin + (size_t)n * LDIM * LDIM + (size_t)blk * 16384);
    float m = -1e30f, s = 0.f;
#pragma unroll
    for (int it = 0; it < 16; it++) {
        float4 v = base[it * 256 + tid];
        float vm = fmaxf(fmaxf(v.x, v.y), fmaxf(v.z, v.w));
        if (vm > m) { s *= __expf(m - vm); m = vm; }
        s += __expf(v.x - m) + __expf(v.y - m) + __expf(v.z - m) + __expf(v.w - m);
    }
    rm[tid] = m; rs[tid] = s;
    __syncthreads();
    for (int str = 128; str > 0; str >>= 1) {
        if (tid < str) {
            float m2 = rm[tid + str], s2 = rs[tid + str];
            float M = fmaxf(rm[tid], m2);
            rs[tid] = rs[tid] * __expf(rm[tid] - M) + s2 * __expf(m2 - M);
            rm[tid] = M;
        }
        __syncthreads();
    }
    if (tid == 0) { g_partm[n * 64 + blk] = rm[0]; g_parts[n * 64 + blk] = rs[0]; }
}

__global__ __launch_bounds__(64) void k_sm_final() {
    __shared__ float rm[64], rs[64];
    const int n = blockIdx.x, tid = threadIdx.x;
    float m = g_partm[n * 64 + tid];
    rm[tid] = m;
    __syncthreads();
    for (int s = 32; s > 0; s >>= 1) {
        if (tid < s) rm[tid] = fmaxf(rm[tid], rm[tid + s]);
        __syncthreads();
    }
    const float M = rm[0];
    __syncthreads();
    rs[tid] = g_parts[n * 64 + tid] * __expf(m - M);
    __syncthreads();
    for (int s = 32; s > 0; s >>= 1) {
        if (tid < s) rs[tid] += rs[tid + s];
        __syncthreads();
    }
    if (tid == 0) { g_M[n] = M; g_invZ[n] = 1.f / rs[0]; }
}

// =====================================================================
extern "C" void kernel_launch(void* const* d_in, const int* in_sizes, int n_in,
                              void* d_out, int out_size) {
    const float* x  = (const float*)d_in[0];
    const float* wt = (const float*)d_in[1];
    const float* wp = (const float*)d_in[2];
    const float* wg = (const float*)d_in[3];
    const float* wr = (const float*)d_in[4];
    float* out = (float*)d_out;
    float* c_out = out;                              // [16,1024,1024]
    float* y_out = out + (size_t)NB * LDIM * LDIM;   // [16,256,32,32]

    gemm_mma<0><<<dim3(8, 6, NB), 256>>>(x, wt, wp, wg, wr, c_out, y_out);
    gemm_mma<1><<<dim3(8, 8, NB), 256>>>(x, wt, wp, wg, wr, c_out, y_out);
    k_sm_partial<<<dim3(64, NB), 256>>>(c_out);
    k_sm_final<<<NB, 64>>>();
    gemm_mma<2><<<dim3(8, 2, NB), 256>>>(x, wt, wp, wg, wr, c_out, y_out);
    gemm_mma<3><<<dim3(8, 2, NB), 256>>>(x, wt, wp, wg, wr, c_out, y_out);
}

// round 12
// speedup vs baseline: 2.2878x; 1.4300x over previous
#include <cuda_runtime.h>
#include <cuda_bf16.h>
#include <stdint.h>
#include <math.h>

#define LDIM 1024
#define CDIM 256
#define NB   16

// ---------------- scratch (device globals) ----------------
__device__ uint16_t g_w_hi[1024 * 256], g_w_lo[1024 * 256];          // wt,wp,wg,wr stacked
__device__ uint16_t g_x_hi[16ull * 256 * 1024], g_x_lo[16ull * 256 * 1024];
__device__ uint16_t g_tpg_hi[3ull * 16 * 256 * 1024], g_tpg_lo[3ull * 16 * 256 * 1024];
__device__ uint16_t g_at_hi[16ull * 256 * 1024], g_at_lo[16ull * 256 * 1024];
__device__ float g_partm[16 * 64], g_parts[16 * 64], g_M[16], g_invZ[16];

// ---------------- helpers ----------------
__device__ __forceinline__ uint32_t smem_u32(const void* p) {
    uint32_t a;
    asm("{ .reg .u64 t; cvta.to.shared.u64 t, %1; cvt.u32.u64 %0, t; }" : "=r"(a) : "l"(p));
    return a;
}
__device__ __forceinline__ void hmma(float* c, const uint32_t* a, const uint32_t* b) {
    asm volatile(
        "mma.sync.aligned.m16n8k16.row.col.f32.bf16.bf16.f32 "
        "{%0,%1,%2,%3}, {%4,%5,%6,%7}, {%8,%9}, {%0,%1,%2,%3};"
        : "+f"(c[0]), "+f"(c[1]), "+f"(c[2]), "+f"(c[3])
        : "r"(a[0]), "r"(a[1]), "r"(a[2]), "r"(a[3]), "r"(b[0]), "r"(b[1]));
}
__device__ __forceinline__ void ldsm4(uint32_t* r, uint32_t addr) {
    asm volatile("ldmatrix.sync.aligned.m8n8.x4.shared.b16 {%0,%1,%2,%3}, [%4];"
                 : "=r"(r[0]), "=r"(r[1]), "=r"(r[2]), "=r"(r[3]) : "r"(addr));
}
__device__ __forceinline__ void ldsm4t(uint32_t* r, uint32_t addr) {
    asm volatile("ldmatrix.sync.aligned.m8n8.x4.trans.shared.b16 {%0,%1,%2,%3}, [%4];"
                 : "=r"(r[0]), "=r"(r[1]), "=r"(r[2]), "=r"(r[3]) : "r"(addr));
}
__device__ __forceinline__ void cp16(uint32_t daddr, const void* src) {
    asm volatile("cp.async.cg.shared.global [%0], [%1], 16;" ::"r"(daddr), "l"(src) : "memory");
}
#define CP_COMMIT() asm volatile("cp.async.commit_group;" ::: "memory")
#define CP_WAIT(n)  asm volatile("cp.async.wait_group %0;" ::"n"(n) : "memory")

__device__ __forceinline__ uint32_t pk2(float a, float b) {
    __nv_bfloat162 t = __floats2bfloat162_rn(a, b);
    return reinterpret_cast<uint32_t&>(t);
}
// write (hi,lo) bf16 pair planes for two consecutive elements
__device__ __forceinline__ void wrpair(uint16_t* hi, uint16_t* lo, float a, float b) {
    float ha = __bfloat162float(__float2bfloat16(a));
    float hb = __bfloat162float(__float2bfloat16(b));
    *(uint32_t*)hi = pk2(a, b);
    *(uint32_t*)lo = pk2(a - ha, b - hb);
}

// ---------------- conversion passes ----------------
__global__ __launch_bounds__(256) void k_cvt_w(const float* __restrict__ wt,
                                               const float* __restrict__ wp,
                                               const float* __restrict__ wg,
                                               const float* __restrict__ wr) {
    int idx = blockIdx.x * 256 + threadIdx.x;   // handles 4 elems
    int e = idx * 4, row = e >> 8, col = e & 255;
    const float* s = (row < 256) ? wt + (size_t)row * 256
                   : (row < 512) ? wp + (size_t)(row - 256) * 256
                   : (row < 768) ? wg + (size_t)(row - 512) * 256
                                 : wr + (size_t)(row - 768) * 256;
    float4 v = *(const float4*)(s + col);
    size_t o = (size_t)row * 256 + col;
    wrpair(g_w_hi + o, g_w_lo + o, v.x, v.y);
    wrpair(g_w_hi + o + 2, g_w_lo + o + 2, v.z, v.w);
}
__global__ __launch_bounds__(256) void k_cvt_x(const float* __restrict__ x) {
    size_t idx = (size_t)blockIdx.x * 256 + threadIdx.x;
    float4 v = ((const float4*)x)[idx];
    size_t o = idx * 4;
    wrpair(g_x_hi + o, g_x_lo + o, v.x, v.y);
    wrpair(g_x_hi + o + 2, g_x_lo + o + 2, v.z, v.w);
}

// =====================================================================
// Pipelined mma.sync GEMM: 128x128 block, BK=16, 8 warps (64x32 warp tile).
// Operands from bf16 hi/lo planes via cp.async; 3-term hi/lo split MMA.
// MODE: 0=tpg  1=c (A = t via ldmatrix.trans)  2=attn (exp fused)  3=y
// =====================================================================
template <int MODE>
__global__ __launch_bounds__(256) void gemm_mma(const float* __restrict__ x,
                                                float* __restrict__ cbuf,
                                                float* __restrict__ ybuf) {
    constexpr int S    = (MODE == 2) ? 64 : 16;
    constexpr int AR   = (MODE == 1) ? 16 : 128;
    constexpr int ASTR = (MODE == 1) ? 136 : 24;
    __shared__ __align__(16) uint16_t Ahs[2][AR * ASTR], Als[2][AR * ASTR];
    __shared__ __align__(16) uint16_t Bhs[2][16 * 136], Bls[2][16 * 136];

    const int tid = threadIdx.x, lane = tid & 31, wid = tid >> 5;
    const int n = blockIdx.z, j0 = blockIdx.x * 128, m0 = blockIdx.y * 128;
    const int wm = (wid & 1) * 64, wn = (wid >> 1) * 32;

    const uint16_t *Aph, *Apl, *Bph = nullptr, *Bpl = nullptr;
    const float* Bf = nullptr;
    float eM = 0.f, iZ = 1.f;
    size_t AKW = 256;
    if (MODE == 0) {
        Aph = g_w_hi + (size_t)m0 * 256;  Apl = g_w_lo + (size_t)m0 * 256;
        Bph = g_x_hi + (size_t)n * CDIM * LDIM;  Bpl = g_x_lo + (size_t)n * CDIM * LDIM;
    } else if (MODE == 1) {
        Aph = g_tpg_hi + (size_t)n * 768 * LDIM;  Apl = g_tpg_lo + (size_t)n * 768 * LDIM;
        Bph = g_tpg_hi + ((size_t)n * 768 + 256) * LDIM;
        Bpl = g_tpg_lo + ((size_t)n * 768 + 256) * LDIM;
    } else if (MODE == 2) {
        Aph = g_tpg_hi + ((size_t)n * 768 + 512 + m0) * LDIM;
        Apl = g_tpg_lo + ((size_t)n * 768 + 512 + m0) * LDIM;
        AKW = 1024;
        Bf = cbuf + (size_t)n * LDIM * LDIM;
        eM = g_M[n]; iZ = g_invZ[n];
    } else {
        Aph = g_w_hi + (size_t)(768 + m0) * 256;  Apl = g_w_lo + (size_t)(768 + m0) * 256;
        Bph = g_at_hi + (size_t)n * CDIM * LDIM;  Bpl = g_at_lo + (size_t)n * CDIM * LDIM;
    }

    float acc[4][4][4];
#pragma unroll
    for (int a = 0; a < 4; a++)
#pragma unroll
        for (int b = 0; b < 4; b++)
#pragma unroll
            for (int c = 0; c < 4; c++) acc[a][b][c] = 0.f;

    float4 vB[2];   // mode2 B register staging

    auto cp_stage = [&](int s) {
        const int buf = s & 1, k0 = s * 16;
        if (MODE == 1) {
            int row = tid >> 4, seg = (tid & 15) * 8;
            size_t so = (size_t)(k0 + row) * LDIM + m0 + seg;
            cp16(smem_u32(&Ahs[buf][row * 136 + seg]), Aph + so);
            cp16(smem_u32(&Als[buf][row * 136 + seg]), Apl + so);
        } else {
            int m = tid >> 1, half = (tid & 1) * 8;
            size_t so = (size_t)m * AKW + k0 + half;
            cp16(smem_u32(&Ahs[buf][m * 24 + half]), Aph + so);
            cp16(smem_u32(&Als[buf][m * 24 + half]), Apl + so);
        }
        if (MODE != 2) {
            int row = tid >> 4, seg = (tid & 15) * 8;
            size_t so = (size_t)(k0 + row) * LDIM + j0 + seg;
            cp16(smem_u32(&Bhs[buf][row * 136 + seg]), Bph + so);
            cp16(smem_u32(&Bls[buf][row * 136 + seg]), Bpl + so);
        }
    };
    auto ldgB = [&](int s) {
        if (MODE == 2) {
            const int k0 = s * 16;
#pragma unroll
            for (int u = 0; u < 2; u++) {
                int vi = tid + 256 * u, k = vi >> 5, j4 = (vi & 31) * 4;
                vB[u] = *(const float4*)(Bf + (size_t)(k0 + k) * LDIM + j0 + j4);
            }
        }
    };
    auto stsB = [&](int s) {
        if (MODE == 2) {
            const int buf = s & 1;
#pragma unroll
            for (int u = 0; u < 2; u++) {
                int vi = tid + 256 * u, k = vi >> 5, j4 = (vi & 31) * 4;
                float e0 = __expf(vB[u].x - eM), e1 = __expf(vB[u].y - eM);
                float e2 = __expf(vB[u].z - eM), e3 = __expf(vB[u].w - eM);
                wrpair(&Bhs[buf][k * 136 + j4],     &Bls[buf][k * 136 + j4],     e0, e1);
                wrpair(&Bhs[buf][k * 136 + j4 + 2], &Bls[buf][k * 136 + j4 + 2], e2, e3);
            }
        }
    };

    // lane-constant ldmatrix offsets
    const int amr = lane & 15, akc = (lane >> 4) * 8;                       // A non-trans
    const int tkr = (lane & 7) + ((lane >> 4) << 3);                        // A trans k-row
    const int tmc = ((lane >> 3) & 1) * 8;                                  // A trans m-col
    const int bkr = lane & 15, bnc = (lane >> 4) * 8;                       // B

    auto compute = [&](int buf) {
        uint32_t abh = smem_u32(Ahs[buf]), abl = smem_u32(Als[buf]);
        uint32_t bbh = smem_u32(Bhs[buf]), bbl = smem_u32(Bls[buf]);
        uint32_t ah[4][4], al[4][4], bh[4][2], bl[4][2];
#pragma unroll
        for (int mf = 0; mf < 4; mf++) {
            if (MODE == 1) {
                uint32_t off = (uint32_t)(tkr * 136 + wm + mf * 16 + tmc) * 2;
                ldsm4t(ah[mf], abh + off);
                ldsm4t(al[mf], abl + off);
            } else {
                uint32_t off = (uint32_t)((wm + mf * 16 + amr) * 24 + akc) * 2;
                ldsm4(ah[mf], abh + off);
                ldsm4(al[mf], abl + off);
            }
        }
#pragma unroll
        for (int nq = 0; nq < 2; nq++) {
            uint32_t off = (uint32_t)(bkr * 136 + wn + nq * 16 + bnc) * 2;
            uint32_t r[4];
            ldsm4t(r, bbh + off);
            bh[nq * 2][0] = r[0]; bh[nq * 2][1] = r[1];
            bh[nq * 2 + 1][0] = r[2]; bh[nq * 2 + 1][1] = r[3];
            ldsm4t(r, bbl + off);
            bl[nq * 2][0] = r[0]; bl[nq * 2][1] = r[1];
            bl[nq * 2 + 1][0] = r[2]; bl[nq * 2 + 1][1] = r[3];
        }
#pragma unroll
        for (int mf = 0; mf < 4; mf++)
#pragma unroll
            for (int nf = 0; nf < 4; nf++) {
                hmma(acc[mf][nf], ah[mf], bh[nf]);
                hmma(acc[mf][nf], ah[mf], bl[nf]);
                hmma(acc[mf][nf], al[mf], bh[nf]);
            }
    };

    // ---- pipeline ----
    cp_stage(0); CP_COMMIT();
    ldgB(0);
    for (int s = 0; s < S; s++) {
        stsB(s);
        if (s + 1 < S) { cp_stage(s + 1); CP_COMMIT(); ldgB(s + 1); }
        if (s + 1 < S) CP_WAIT(1); else CP_WAIT(0);
        __syncthreads();
        compute(s & 1);
        __syncthreads();
    }

    // ---- epilogue ----
    const int g8 = lane >> 2, tg = lane & 3;
#pragma unroll
    for (int mf = 0; mf < 4; mf++)
#pragma unroll
        for (int nf = 0; nf < 4; nf++) {
            int r0 = wm + mf * 16 + g8, cc = wn + nf * 8 + tg * 2;
#pragma unroll
            for (int h = 0; h < 2; h++) {
                int row = r0 + h * 8;
                float f0 = acc[mf][nf][h * 2], f1 = acc[mf][nf][h * 2 + 1];
                if (MODE == 0) {
                    size_t o = ((size_t)n * 768 + m0 + row) * LDIM + j0 + cc;
                    wrpair(g_tpg_hi + o, g_tpg_lo + o, f0, f1);
                } else if (MODE == 1) {
                    *(float2*)(cbuf + ((size_t)n * LDIM + m0 + row) * LDIM + j0 + cc) =
                        make_float2(f0, f1);
                } else if (MODE == 2) {
                    f0 *= iZ; f1 *= iZ;
                    size_t o = ((size_t)n * CDIM + m0 + row) * LDIM + j0 + cc;
                    wrpair(g_at_hi + o, g_at_lo + o, f0, f1);
                } else {
                    const float2 xv = *(const float2*)(x + ((size_t)n * CDIM + m0 + row) * LDIM + j0 + cc);
                    *(float2*)(ybuf + ((size_t)n * CDIM + m0 + row) * LDIM + j0 + cc) =
                        make_float2(f0 + xv.x, f1 + xv.y);
                }
            }
        }
}

// ---------------- softmax stats ----------------
__global__ __launch_bounds__(256) void k_sm_partial(const float* __restrict__ cin) {
    __shared__ float rm[256], rs[256];
    const int n = blockIdx.y, blk = blockIdx.x, tid = threadIdx.x;
    const float4* base = (const float4*)(cin + (size_t)n * LDIM * LDIM + (size_t)blk * 16384);
    float m = -1e30f, s = 0.f;
#pragma unroll
    for (int it = 0; it < 16; it++) {
        float4 v = base[it * 256 + tid];
        float vm = fmaxf(fmaxf(v.x, v.y), fmaxf(v.z, v.w));
        if (vm > m) { s *= __expf(m - vm); m = vm; }
        s += __expf(v.x - m) + __expf(v.y - m) + __expf(v.z - m) + __expf(v.w - m);
    }
    rm[tid] = m; rs[tid] = s;
    __syncthreads();
    for (int str = 128; str > 0; str >>= 1) {
        if (tid < str) {
            float m2 = rm[tid + str], s2 = rs[tid + str];
            float M = fmaxf(rm[tid], m2);
            rs[tid] = rs[tid] * __expf(rm[tid] - M) + s2 * __expf(m2 - M);
            rm[tid] = M;
        }
        __syncthreads();
    }
    if (tid == 0) { g_partm[n * 64 + blk] = rm[0]; g_parts[n * 64 + blk] = rs[0]; }
}

__global__ __launch_bounds__(64) void k_sm_final() {
    __shared__ float rm[64], rs[64];
    const int n = blockIdx.x, tid = threadIdx.x;
    float m = g_partm[n * 64 + tid];
    rm[tid] = m;
    __syncthreads();
    for (int s = 32; s > 0; s >>= 1) {
        if (tid < s) rm[tid] = fmaxf(rm[tid], rm[tid + s]);
        __syncthreads();
    }
    const float M = rm[0];
    __syncthreads();
    rs[tid] = g_parts[n * 64 + tid] * __expf(m - M);
    __syncthreads();
    for (int s = 32; s > 0; s >>= 1) {
        if (tid < s) rs[tid] += rs[tid + s];
        __syncthreads();
    }
    if (tid == 0) { g_M[n] = M; g_invZ[n] = 1.f / rs[0]; }
}

// =====================================================================
extern "C" void kernel_launch(void* const* d_in, const int* in_sizes, int n_in,
                              void* d_out, int out_size) {
    const float* x  = (const float*)d_in[0];
    const float* wt = (const float*)d_in[1];
    const float* wp = (const float*)d_in[2];
    const float* wg = (const float*)d_in[3];
    const float* wr = (const float*)d_in[4];
    float* out = (float*)d_out;
    float* c_out = out;                              // [16,1024,1024]
    float* y_out = out + (size_t)NB * LDIM * LDIM;   // [16,256,32,32]

    k_cvt_w<<<256, 256>>>(wt, wp, wg, wr);
    k_cvt_x<<<4096, 256>>>(x);
    gemm_mma<0><<<dim3(8, 6, NB), 256>>>(x, c_out, y_out);
    gemm_mma<1><<<dim3(8, 8, NB), 256>>>(x, c_out, y_out);
    k_sm_partial<<<dim3(64, NB), 256>>>(c_out);
    k_sm_final<<<NB, 64>>>();
    gemm_mma<2><<<dim3(8, 2, NB), 256>>>(x, c_out, y_out);
    gemm_mma<3><<<dim3(8, 2, NB), 256>>>(x, c_out, y_out);
}

// round 13
// speedup vs baseline: 2.5424x; 1.1113x over previous
#include <cuda_runtime.h>
#include <cuda_bf16.h>
#include <stdint.h>
#include <math.h>

#define LDIM 1024
#define CDIM 256
#define NB   16

// ---------------- scratch (device globals) ----------------
__device__ uint16_t g_w_hi[1024 * 256], g_w_lo[1024 * 256];          // wt,wp,wg,wr stacked
__device__ uint16_t g_x_hi[16ull * 256 * 1024], g_x_lo[16ull * 256 * 1024];
__device__ uint16_t g_tpg_hi[3ull * 16 * 256 * 1024], g_tpg_lo[3ull * 16 * 256 * 1024];
__device__ uint16_t g_at_hi[16ull * 256 * 1024], g_at_lo[16ull * 256 * 1024];
__device__ float g_partm[16 * 64], g_parts[16 * 64], g_M[16], g_invZ[16];

// ---------------- helpers ----------------
__device__ __forceinline__ uint32_t smem_u32(const void* p) {
    uint32_t a;
    asm("{ .reg .u64 t; cvta.to.shared.u64 t, %1; cvt.u32.u64 %0, t; }" : "=r"(a) : "l"(p));
    return a;
}
__device__ __forceinline__ void hmma(float* c, const uint32_t* a, const uint32_t* b) {
    asm volatile(
        "mma.sync.aligned.m16n8k16.row.col.f32.bf16.bf16.f32 "
        "{%0,%1,%2,%3}, {%4,%5,%6,%7}, {%8,%9}, {%0,%1,%2,%3};"
        : "+f"(c[0]), "+f"(c[1]), "+f"(c[2]), "+f"(c[3])
        : "r"(a[0]), "r"(a[1]), "r"(a[2]), "r"(a[3]), "r"(b[0]), "r"(b[1]));
}
__device__ __forceinline__ void ldsm4(uint32_t* r, uint32_t addr) {
    asm volatile("ldmatrix.sync.aligned.m8n8.x4.shared.b16 {%0,%1,%2,%3}, [%4];"
                 : "=r"(r[0]), "=r"(r[1]), "=r"(r[2]), "=r"(r[3]) : "r"(addr));
}
__device__ __forceinline__ void ldsm4t(uint32_t* r, uint32_t addr) {
    asm volatile("ldmatrix.sync.aligned.m8n8.x4.trans.shared.b16 {%0,%1,%2,%3}, [%4];"
                 : "=r"(r[0]), "=r"(r[1]), "=r"(r[2]), "=r"(r[3]) : "r"(addr));
}
__device__ __forceinline__ void cp16(uint32_t daddr, const void* src) {
    asm volatile("cp.async.cg.shared.global [%0], [%1], 16;" ::"r"(daddr), "l"(src) : "memory");
}
#define CP_COMMIT() asm volatile("cp.async.commit_group;" ::: "memory")
#define CP_WAIT(n)  asm volatile("cp.async.wait_group %0;" ::"n"(n) : "memory")

__device__ __forceinline__ uint32_t pk2(float a, float b) {
    __nv_bfloat162 t = __floats2bfloat162_rn(a, b);
    return reinterpret_cast<uint32_t&>(t);
}
__device__ __forceinline__ void wrpair(uint16_t* hi, uint16_t* lo, float a, float b) {
    float ha = __bfloat162float(__float2bfloat16(a));
    float hb = __bfloat162float(__float2bfloat16(b));
    *(uint32_t*)hi = pk2(a, b);
    *(uint32_t*)lo = pk2(a - ha, b - hb);
}

// ---------------- conversion passes ----------------
__global__ __launch_bounds__(256) void k_cvt_w(const float* __restrict__ wt,
                                               const float* __restrict__ wp,
                                               const float* __restrict__ wg,
                                               const float* __restrict__ wr) {
    int idx = blockIdx.x * 256 + threadIdx.x;
    int e = idx * 4, row = e >> 8, col = e & 255;
    const float* s = (row < 256) ? wt + (size_t)row * 256
                   : (row < 512) ? wp + (size_t)(row - 256) * 256
                   : (row < 768) ? wg + (size_t)(row - 512) * 256
                                 : wr + (size_t)(row - 768) * 256;
    float4 v = *(const float4*)(s + col);
    size_t o = (size_t)row * 256 + col;
    wrpair(g_w_hi + o, g_w_lo + o, v.x, v.y);
    wrpair(g_w_hi + o + 2, g_w_lo + o + 2, v.z, v.w);
}
__global__ __launch_bounds__(256) void k_cvt_x(const float* __restrict__ x) {
    size_t idx = (size_t)blockIdx.x * 256 + threadIdx.x;
    float4 v = ((const float4*)x)[idx];
    size_t o = idx * 4;
    wrpair(g_x_hi + o, g_x_lo + o, v.x, v.y);
    wrpair(g_x_hi + o + 2, g_x_lo + o + 2, v.z, v.w);
}

// =====================================================================
// Pipelined mma.sync GEMM: 128x128 block, BK=32, 4-stage ring, ONE sync
// per stage. 8 warps (64x32 warp tile), bf16 hi/lo 3-term split.
// MODE: 0=tpg  1=c (A = t via ldmatrix.trans)  2=attn (exp fused)  3=y
// =====================================================================
template <int MODE>
__global__ __launch_bounds__(256) void gemm_mma(const float* __restrict__ x,
                                                float* __restrict__ cbuf,
                                                float* __restrict__ ybuf) {
    constexpr int S     = (MODE == 2) ? 32 : 8;          // K/32 stages
    constexpr int APL   = (MODE == 1) ? 32 * 136 : 128 * 40;   // A plane elems
    constexpr int BPL   = 32 * 136;
    constexpr int STAGE = 2 * APL + 2 * BPL;             // elems per stage
    extern __shared__ __align__(16) uint16_t smbuf[];

    const int tid = threadIdx.x, lane = tid & 31, wid = tid >> 5;
    const int n = blockIdx.z, j0 = blockIdx.x * 128, m0 = blockIdx.y * 128;
    const int wm = (wid & 1) * 64, wn = (wid >> 1) * 32;

    const uint16_t *Aph, *Apl, *Bph = nullptr, *Bpl = nullptr;
    const float* Bf = nullptr;
    float eM = 0.f, iZ = 1.f;
    size_t AKW = 256;
    if (MODE == 0) {
        Aph = g_w_hi + (size_t)m0 * 256;  Apl = g_w_lo + (size_t)m0 * 256;
        Bph = g_x_hi + (size_t)n * CDIM * LDIM;  Bpl = g_x_lo + (size_t)n * CDIM * LDIM;
    } else if (MODE == 1) {
        Aph = g_tpg_hi + (size_t)n * 768 * LDIM;  Apl = g_tpg_lo + (size_t)n * 768 * LDIM;
        Bph = g_tpg_hi + ((size_t)n * 768 + 256) * LDIM;
        Bpl = g_tpg_lo + ((size_t)n * 768 + 256) * LDIM;
    } else if (MODE == 2) {
        Aph = g_tpg_hi + ((size_t)n * 768 + 512 + m0) * LDIM;
        Apl = g_tpg_lo + ((size_t)n * 768 + 512 + m0) * LDIM;
        AKW = 1024;
        Bf = cbuf + (size_t)n * LDIM * LDIM;
        eM = g_M[n]; iZ = g_invZ[n];
    } else {
        Aph = g_w_hi + (size_t)(768 + m0) * 256;  Apl = g_w_lo + (size_t)(768 + m0) * 256;
        Bph = g_at_hi + (size_t)n * CDIM * LDIM;  Bpl = g_at_lo + (size_t)n * CDIM * LDIM;
    }

    float acc[4][4][4];
#pragma unroll
    for (int a = 0; a < 4; a++)
#pragma unroll
        for (int b = 0; b < 4; b++)
#pragma unroll
            for (int c = 0; c < 4; c++) acc[a][b][c] = 0.f;

    float4 vB[4];   // mode2 B register staging (32x128 fp32 tile / 256 thr)

    auto cp_stage = [&](int s) {
        const int k0 = s * 32;
        uint16_t* st = smbuf + (size_t)(s & 3) * STAGE;
        uint16_t* Ah = st;            uint16_t* Al = st + APL;
        uint16_t* Bh = st + 2 * APL;  uint16_t* Bl = st + 2 * APL + BPL;
        if (MODE == 1) {
#pragma unroll
            for (int u = 0; u < 2; u++) {
                int idx = tid + 256 * u;                   // 512 chunks
                int row = idx >> 4, seg = (idx & 15) * 8;
                size_t so = (size_t)(k0 + row) * LDIM + m0 + seg;
                cp16(smem_u32(Ah + row * 136 + seg), Aph + so);
                cp16(smem_u32(Al + row * 136 + seg), Apl + so);
            }
        } else {
#pragma unroll
            for (int u = 0; u < 2; u++) {
                int idx = tid + 256 * u;
                int m = idx >> 2, kseg = (idx & 3) * 8;
                size_t so = (size_t)m * AKW + k0 + kseg;
                cp16(smem_u32(Ah + m * 40 + kseg), Aph + so);
                cp16(smem_u32(Al + m * 40 + kseg), Apl + so);
            }
        }
        if (MODE != 2) {
#pragma unroll
            for (int u = 0; u < 2; u++) {
                int idx = tid + 256 * u;
                int row = idx >> 4, seg = (idx & 15) * 8;
                size_t so = (size_t)(k0 + row) * LDIM + j0 + seg;
                cp16(smem_u32(Bh + row * 136 + seg), Bph + so);
                cp16(smem_u32(Bl + row * 136 + seg), Bpl + so);
            }
        }
    };
    auto ldgB = [&](int s) {
        if (MODE == 2 && s < S) {
            const int k0 = s * 32;
#pragma unroll
            for (int u = 0; u < 4; u++) {
                int vi = tid + 256 * u, k = vi >> 5, j4 = (vi & 31) * 4;
                vB[u] = *(const float4*)(Bf + (size_t)(k0 + k) * LDIM + j0 + j4);
            }
        }
    };
    auto stsB = [&](int s) {
        if (MODE == 2) {
            uint16_t* st = smbuf + (size_t)(s & 3) * STAGE;
            uint16_t* Bh = st + 2 * APL;  uint16_t* Bl = st + 2 * APL + BPL;
#pragma unroll
            for (int u = 0; u < 4; u++) {
                int vi = tid + 256 * u, k = vi >> 5, j4 = (vi & 31) * 4;
                float e0 = __expf(vB[u].x - eM), e1 = __expf(vB[u].y - eM);
                float e2 = __expf(vB[u].z - eM), e3 = __expf(vB[u].w - eM);
                wrpair(Bh + k * 136 + j4,     Bl + k * 136 + j4,     e0, e1);
                wrpair(Bh + k * 136 + j4 + 2, Bl + k * 136 + j4 + 2, e2, e3);
            }
        }
    };

    // lane-constant ldmatrix offsets
    const int amr = lane & 15, akc = (lane >> 4) * 8;                 // A non-trans
    const int tkr = (lane & 7) + ((lane >> 4) << 3);                  // A trans k-row
    const int tmc = ((lane >> 3) & 1) * 8;                            // A trans m-col
    const int bkr = lane & 15, bnc = (lane >> 4) * 8;                 // B

    auto compute = [&](int buf) {
        uint16_t* st = smbuf + (size_t)buf * STAGE;
        uint32_t abh = smem_u32(st),            abl = smem_u32(st + APL);
        uint32_t bbh = smem_u32(st + 2 * APL),  bbl = smem_u32(st + 2 * APL + BPL);
#pragma unroll
        for (int ks = 0; ks < 32; ks += 16) {
            uint32_t ah[4][4], al[4][4], bh[4][2], bl[4][2];
#pragma unroll
            for (int mf = 0; mf < 4; mf++) {
                if (MODE == 1) {
                    uint32_t off = (uint32_t)((ks + tkr) * 136 + wm + mf * 16 + tmc) * 2;
                    ldsm4t(ah[mf], abh + off);
                    ldsm4t(al[mf], abl + off);
                } else {
                    uint32_t off = (uint32_t)((wm + mf * 16 + amr) * 40 + ks + akc) * 2;
                    ldsm4(ah[mf], abh + off);
                    ldsm4(al[mf], abl + off);
                }
            }
#pragma unroll
            for (int nq = 0; nq < 2; nq++) {
                uint32_t off = (uint32_t)((ks + bkr) * 136 + wn + nq * 16 + bnc) * 2;
                uint32_t r[4];
                ldsm4t(r, bbh + off);
                bh[nq * 2][0] = r[0]; bh[nq * 2][1] = r[1];
                bh[nq * 2 + 1][0] = r[2]; bh[nq * 2 + 1][1] = r[3];
                ldsm4t(r, bbl + off);
                bl[nq * 2][0] = r[0]; bl[nq * 2][1] = r[1];
                bl[nq * 2 + 1][0] = r[2]; bl[nq * 2 + 1][1] = r[3];
            }
#pragma unroll
            for (int mf = 0; mf < 4; mf++)
#pragma unroll
                for (int nf = 0; nf < 4; nf++) {
                    hmma(acc[mf][nf], ah[mf], bh[nf]);
                    hmma(acc[mf][nf], ah[mf], bl[nf]);
                    hmma(acc[mf][nf], al[mf], bh[nf]);
                }
        }
    };

    // ---- pipeline: 4-stage ring, prefetch distance 2, one sync/stage ----
    cp_stage(0); CP_COMMIT();
    cp_stage(1); CP_COMMIT();
    ldgB(0);
    for (int s = 0; s < S; s++) {
        stsB(s);
        ldgB(s + 1);
        if (s + 2 < S) { cp_stage(s + 2); CP_COMMIT(); CP_WAIT(2); }
        else if (s + 1 < S) { CP_WAIT(1); }
        else { CP_WAIT(0); }
        __syncthreads();
        compute(s & 3);
    }

    // ---- epilogue ----
    const int g8 = lane >> 2, tg = lane & 3;
#pragma unroll
    for (int mf = 0; mf < 4; mf++)
#pragma unroll
        for (int nf = 0; nf < 4; nf++) {
            int r0 = wm + mf * 16 + g8, cc = wn + nf * 8 + tg * 2;
#pragma unroll
            for (int h = 0; h < 2; h++) {
                int row = r0 + h * 8;
                float f0 = acc[mf][nf][h * 2], f1 = acc[mf][nf][h * 2 + 1];
                if (MODE == 0) {
                    size_t o = ((size_t)n * 768 + m0 + row) * LDIM + j0 + cc;
                    wrpair(g_tpg_hi + o, g_tpg_lo + o, f0, f1);
                } else if (MODE == 1) {
                    *(float2*)(cbuf + ((size_t)n * LDIM + m0 + row) * LDIM + j0 + cc) =
                        make_float2(f0, f1);
                } else if (MODE == 2) {
                    f0 *= iZ; f1 *= iZ;
                    size_t o = ((size_t)n * CDIM + m0 + row) * LDIM + j0 + cc;
                    wrpair(g_at_hi + o, g_at_lo + o, f0, f1);
                } else {
                    const float2 xv = *(const float2*)(x + ((size_t)n * CDIM + m0 + row) * LDIM + j0 + cc);
                    *(float2*)(ybuf + ((size_t)n * CDIM + m0 + row) * LDIM + j0 + cc) =
                        make_float2(f0 + xv.x, f1 + xv.y);
                }
            }
        }
}

// ---------------- softmax stats ----------------
__global__ __launch_bounds__(256) void k_sm_partial(const float* __restrict__ cin) {
    __shared__ float rm[256], rs[256];
    const int n = blockIdx.y, blk = blockIdx.x, tid = threadIdx.x;
    const float4* base = (const float4*)(cin + (size_t)n * LDIM * LDIM + (size_t)blk * 16384);
    float m = -1e30f, s = 0.f;
#pragma unroll
    for (int it = 0; it < 16; it++) {
        float4 v = base[it * 256 + tid];
        float vm = fmaxf(fmaxf(v.x, v.y), fmaxf(v.z, v.w));
        if (vm > m) { s *= __expf(m - vm); m = vm; }
        s += __expf(v.x - m) + __expf(v.y - m) + __expf(v.z - m) + __expf(v.w - m);
    }
    rm[tid] = m; rs[tid] = s;
    __syncthreads();
    for (int str = 128; str > 0; str >>= 1) {
        if (tid < str) {
            float m2 = rm[tid + str], s2 = rs[tid + str];
            float M = fmaxf(rm[tid], m2);
            rs[tid] = rs[tid] * __expf(rm[tid] - M) + s2 * __expf(m2 - M);
            rm[tid] = M;
        }
        __syncthreads();
    }
    if (tid == 0) { g_partm[n * 64 + blk] = rm[0]; g_parts[n * 64 + blk] = rs[0]; }
}

__global__ __launch_bounds__(64) void k_sm_final() {
    __shared__ float rm[64], rs[64];
    const int n = blockIdx.x, tid = threadIdx.x;
    float m = g_partm[n * 64 + tid];
    rm[tid] = m;
    __syncthreads();
    for (int s = 32; s > 0; s >>= 1) {
        if (tid < s) rm[tid] = fmaxf(rm[tid], rm[tid + s]);
        __syncthreads();
    }
    const float M = rm[0];
    __syncthreads();
    rs[tid] = g_parts[n * 64 + tid] * __expf(m - M);
    __syncthreads();
    for (int s = 32; s > 0; s >>= 1) {
        if (tid < s) rs[tid] += rs[tid + s];
        __syncthreads();
    }
    if (tid == 0) { g_M[n] = M; g_invZ[n] = 1.f / rs[0]; }
}

// =====================================================================
extern "C" void kernel_launch(void* const* d_in, const int* in_sizes, int n_in,
                              void* d_out, int out_size) {
    const float* x  = (const float*)d_in[0];
    const float* wt = (const float*)d_in[1];
    const float* wp = (const float*)d_in[2];
    const float* wg = (const float*)d_in[3];
    const float* wr = (const float*)d_in[4];
    float* out = (float*)d_out;
    float* c_out = out;                              // [16,1024,1024]
    float* y_out = out + (size_t)NB * LDIM * LDIM;   // [16,256,32,32]

    constexpr int SM_A  = 4 * (2 * 128 * 40 + 2 * 32 * 136) * 2;   // modes 0,2,3
    constexpr int SM_T  = 4 * (2 * 32 * 136 + 2 * 32 * 136) * 2;   // mode 1
    cudaFuncSetAttribute(gemm_mma<0>, cudaFuncAttributeMaxDynamicSharedMemorySize, SM_A);
    cudaFuncSetAttribute(gemm_mma<1>, cudaFuncAttributeMaxDynamicSharedMemorySize, SM_T);
    cudaFuncSetAttribute(gemm_mma<2>, cudaFuncAttributeMaxDynamicSharedMemorySize, SM_A);
    cudaFuncSetAttribute(gemm_mma<3>, cudaFuncAttributeMaxDynamicSharedMemorySize, SM_A);

    k_cvt_w<<<256, 256>>>(wt, wp, wg, wr);
    k_cvt_x<<<4096, 256>>>(x);
    gemm_mma<0><<<dim3(8, 6, NB), 256, SM_A>>>(x, c_out, y_out);
    gemm_mma<1><<<dim3(8, 8, NB), 256, SM_T>>>(x, c_out, y_out);
    k_sm_partial<<<dim3(64, NB), 256>>>(c_out);
    k_sm_final<<<NB, 64>>>();
    gemm_mma<2><<<dim3(8, 2, NB), 256, SM_A>>>(x, c_out, y_out);
    gemm_mma<3><<<dim3(8, 2, NB), 256, SM_A>>>(x, c_out, y_out);
}

// round 14
// speedup vs baseline: 2.8647x; 1.1267x over previous
#include <cuda_runtime.h>
#include <cuda_bf16.h>
#include <stdint.h>
#include <math.h>

#define LDIM 1024
#define CDIM 256
#define NB   16

// ---------------- scratch (device globals) ----------------
__device__ uint16_t g_w_hi[1024 * 256], g_w_lo[1024 * 256];          // wt,wp,wg,wr stacked
__device__ uint16_t g_x_hi[16ull * 256 * 1024], g_x_lo[16ull * 256 * 1024];
__device__ uint16_t g_tpg_hi[3ull * 16 * 256 * 1024], g_tpg_lo[3ull * 16 * 256 * 1024];
__device__ uint16_t g_at_hi[16ull * 256 * 1024], g_at_lo[16ull * 256 * 1024];
__device__ float g_partm[16 * 64], g_parts[16 * 64], g_M[16], g_invZ[16];

// ---------------- helpers ----------------
__device__ __forceinline__ uint32_t smem_u32(const void* p) {
    uint32_t a;
    asm("{ .reg .u64 t; cvta.to.shared.u64 t, %1; cvt.u32.u64 %0, t; }" : "=r"(a) : "l"(p));
    return a;
}
__device__ __forceinline__ void hmma(float* c, const uint32_t* a, const uint32_t* b) {
    asm volatile(
        "mma.sync.aligned.m16n8k16.row.col.f32.bf16.bf16.f32 "
        "{%0,%1,%2,%3}, {%4,%5,%6,%7}, {%8,%9}, {%0,%1,%2,%3};"
        : "+f"(c[0]), "+f"(c[1]), "+f"(c[2]), "+f"(c[3])
        : "r"(a[0]), "r"(a[1]), "r"(a[2]), "r"(a[3]), "r"(b[0]), "r"(b[1]));
}
__device__ __forceinline__ void ldsm4(uint32_t* r, uint32_t addr) {
    asm volatile("ldmatrix.sync.aligned.m8n8.x4.shared.b16 {%0,%1,%2,%3}, [%4];"
                 : "=r"(r[0]), "=r"(r[1]), "=r"(r[2]), "=r"(r[3]) : "r"(addr));
}
__device__ __forceinline__ void ldsm4t(uint32_t* r, uint32_t addr) {
    asm volatile("ldmatrix.sync.aligned.m8n8.x4.trans.shared.b16 {%0,%1,%2,%3}, [%4];"
                 : "=r"(r[0]), "=r"(r[1]), "=r"(r[2]), "=r"(r[3]) : "r"(addr));
}
__device__ __forceinline__ void cp16(uint32_t daddr, const void* src) {
    asm volatile("cp.async.cg.shared.global [%0], [%1], 16;" ::"r"(daddr), "l"(src) : "memory");
}
#define CP_COMMIT() asm volatile("cp.async.commit_group;" ::: "memory")
#define CP_WAIT(n)  asm volatile("cp.async.wait_group %0;" ::"n"(n) : "memory")

__device__ __forceinline__ uint32_t pk2(float a, float b) {
    __nv_bfloat162 t = __floats2bfloat162_rn(a, b);
    return reinterpret_cast<uint32_t&>(t);
}
__device__ __forceinline__ void wrpair(uint16_t* hi, uint16_t* lo, float a, float b) {
    float ha = __bfloat162float(__float2bfloat16(a));
    float hb = __bfloat162float(__float2bfloat16(b));
    *(uint32_t*)hi = pk2(a, b);
    *(uint32_t*)lo = pk2(a - ha, b - hb);
}

// ---------------- conversion passes ----------------
__global__ __launch_bounds__(256) void k_cvt_w(const float* __restrict__ wt,
                                               const float* __restrict__ wp,
                                               const float* __restrict__ wg,
                                               const float* __restrict__ wr) {
    int idx = blockIdx.x * 256 + threadIdx.x;
    int e = idx * 4, row = e >> 8, col = e & 255;
    const float* s = (row < 256) ? wt + (size_t)row * 256
                   : (row < 512) ? wp + (size_t)(row - 256) * 256
                   : (row < 768) ? wg + (size_t)(row - 512) * 256
                                 : wr + (size_t)(row - 768) * 256;
    float4 v = *(const float4*)(s + col);
    size_t o = (size_t)row * 256 + col;
    wrpair(g_w_hi + o, g_w_lo + o, v.x, v.y);
    wrpair(g_w_hi + o + 2, g_w_lo + o + 2, v.z, v.w);
}
__global__ __launch_bounds__(256) void k_cvt_x(const float* __restrict__ x) {
    size_t idx = (size_t)blockIdx.x * 256 + threadIdx.x;
    float4 v = ((const float4*)x)[idx];
    size_t o = idx * 4;
    wrpair(g_x_hi + o, g_x_lo + o, v.x, v.y);
    wrpair(g_x_hi + o + 2, g_x_lo + o + 2, v.z, v.w);
}

// =====================================================================
// Pipelined mma.sync GEMM: 128x128 block, BK=16, 4-stage ring, one sync
// per stage, 2 CTAs/SM. 8 warps (64x32 warp tile), bf16 hi/lo 3-term split.
// MODE: 0=tpg  1=c (A = t via ldmatrix.trans, fused softmax partial)
//       2=attn (exp fused)  3=y
// =====================================================================
template <int MODE>
__global__ __launch_bounds__(256, 2) void gemm_mma(const float* __restrict__ x,
                                                   float* __restrict__ cbuf,
                                                   float* __restrict__ ybuf) {
    constexpr int S     = (MODE == 2) ? 64 : 16;               // K/16 stages
    constexpr int APL   = (MODE == 1) ? 16 * 136 : 128 * 24;   // A plane elems
    constexpr int BPL   = 16 * 136;
    constexpr int STAGE = 2 * APL + 2 * BPL;
    extern __shared__ __align__(16) uint16_t smbuf[];

    const int tid = threadIdx.x, lane = tid & 31, wid = tid >> 5;
    const int n = blockIdx.z, j0 = blockIdx.x * 128, m0 = blockIdx.y * 128;
    const int wm = (wid & 1) * 64, wn = (wid >> 1) * 32;

    const uint16_t *Aph, *Apl, *Bph = nullptr, *Bpl = nullptr;
    const float* Bf = nullptr;
    float eM = 0.f, iZ = 1.f;
    size_t AKW = 256;
    if (MODE == 0) {
        Aph = g_w_hi + (size_t)m0 * 256;  Apl = g_w_lo + (size_t)m0 * 256;
        Bph = g_x_hi + (size_t)n * CDIM * LDIM;  Bpl = g_x_lo + (size_t)n * CDIM * LDIM;
    } else if (MODE == 1) {
        Aph = g_tpg_hi + (size_t)n * 768 * LDIM;  Apl = g_tpg_lo + (size_t)n * 768 * LDIM;
        Bph = g_tpg_hi + ((size_t)n * 768 + 256) * LDIM;
        Bpl = g_tpg_lo + ((size_t)n * 768 + 256) * LDIM;
    } else if (MODE == 2) {
        Aph = g_tpg_hi + ((size_t)n * 768 + 512 + m0) * LDIM;
        Apl = g_tpg_lo + ((size_t)n * 768 + 512 + m0) * LDIM;
        AKW = 1024;
        Bf = cbuf + (size_t)n * LDIM * LDIM;
        eM = g_M[n]; iZ = g_invZ[n];
    } else {
        Aph = g_w_hi + (size_t)(768 + m0) * 256;  Apl = g_w_lo + (size_t)(768 + m0) * 256;
        Bph = g_at_hi + (size_t)n * CDIM * LDIM;  Bpl = g_at_lo + (size_t)n * CDIM * LDIM;
    }

    float acc[4][4][4];
#pragma unroll
    for (int a = 0; a < 4; a++)
#pragma unroll
        for (int b = 0; b < 4; b++)
#pragma unroll
            for (int c = 0; c < 4; c++) acc[a][b][c] = 0.f;

    float4 vB[2];   // mode2 B register staging (16x128 fp32 / 256 thr)

    auto cp_stage = [&](int s) {
        const int k0 = s * 16;
        uint16_t* st = smbuf + (size_t)(s & 3) * STAGE;
        uint16_t* Ah = st;            uint16_t* Al = st + APL;
        uint16_t* Bh = st + 2 * APL;  uint16_t* Bl = st + 2 * APL + BPL;
        if (MODE == 1) {
            int row = tid >> 4, seg = (tid & 15) * 8;
            size_t so = (size_t)(k0 + row) * LDIM + m0 + seg;
            cp16(smem_u32(Ah + row * 136 + seg), Aph + so);
            cp16(smem_u32(Al + row * 136 + seg), Apl + so);
        } else {
            int m = tid >> 1, kseg = (tid & 1) * 8;
            size_t so = (size_t)m * AKW + k0 + kseg;
            cp16(smem_u32(Ah + m * 24 + kseg), Aph + so);
            cp16(smem_u32(Al + m * 24 + kseg), Apl + so);
        }
        if (MODE != 2) {
            int row = tid >> 4, seg = (tid & 15) * 8;
            size_t so = (size_t)(k0 + row) * LDIM + j0 + seg;
            cp16(smem_u32(Bh + row * 136 + seg), Bph + so);
            cp16(smem_u32(Bl + row * 136 + seg), Bpl + so);
        }
    };
    auto ldgB = [&](int s) {
        if (MODE == 2 && s < S) {
            const int k0 = s * 16;
#pragma unroll
            for (int u = 0; u < 2; u++) {
                int vi = tid + 256 * u, k = vi >> 5, j4 = (vi & 31) * 4;
                vB[u] = *(const float4*)(Bf + (size_t)(k0 + k) * LDIM + j0 + j4);
            }
        }
    };
    auto stsB = [&](int s) {
        if (MODE == 2) {
            uint16_t* st = smbuf + (size_t)(s & 3) * STAGE;
            uint16_t* Bh = st + 2 * APL;  uint16_t* Bl = st + 2 * APL + BPL;
#pragma unroll
            for (int u = 0; u < 2; u++) {
                int vi = tid + 256 * u, k = vi >> 5, j4 = (vi & 31) * 4;
                float e0 = __expf(vB[u].x - eM), e1 = __expf(vB[u].y - eM);
                float e2 = __expf(vB[u].z - eM), e3 = __expf(vB[u].w - eM);
                wrpair(Bh + k * 136 + j4,     Bl + k * 136 + j4,     e0, e1);
                wrpair(Bh + k * 136 + j4 + 2, Bl + k * 136 + j4 + 2, e2, e3);
            }
        }
    };

    // lane-constant ldmatrix offsets
    const int amr = lane & 15, akc = (lane >> 4) * 8;                 // A non-trans
    const int tkr = (lane & 7) + ((lane >> 4) << 3);                  // A trans k-row
    const int tmc = ((lane >> 3) & 1) * 8;                            // A trans m-col
    const int bkr = lane & 15, bnc = (lane >> 4) * 8;                 // B

    auto compute = [&](int buf) {
        uint16_t* st = smbuf + (size_t)buf * STAGE;
        uint32_t abh = smem_u32(st),            abl = smem_u32(st + APL);
        uint32_t bbh = smem_u32(st + 2 * APL),  bbl = smem_u32(st + 2 * APL + BPL);
        uint32_t ah[4][4], al[4][4], bh[4][2], bl[4][2];
#pragma unroll
        for (int mf = 0; mf < 4; mf++) {
            if (MODE == 1) {
                uint32_t off = (uint32_t)(tkr * 136 + wm + mf * 16 + tmc) * 2;
                ldsm4t(ah[mf], abh + off);
                ldsm4t(al[mf], abl + off);
            } else {
                uint32_t off = (uint32_t)((wm + mf * 16 + amr) * 24 + akc) * 2;
                ldsm4(ah[mf], abh + off);
                ldsm4(al[mf], abl + off);
            }
        }
#pragma unroll
        for (int nq = 0; nq < 2; nq++) {
            uint32_t off = (uint32_t)(bkr * 136 + wn + nq * 16 + bnc) * 2;
            uint32_t r[4];
            ldsm4t(r, bbh + off);
            bh[nq * 2][0] = r[0]; bh[nq * 2][1] = r[1];
            bh[nq * 2 + 1][0] = r[2]; bh[nq * 2 + 1][1] = r[3];
            ldsm4t(r, bbl + off);
            bl[nq * 2][0] = r[0]; bl[nq * 2][1] = r[1];
            bl[nq * 2 + 1][0] = r[2]; bl[nq * 2 + 1][1] = r[3];
        }
#pragma unroll
        for (int mf = 0; mf < 4; mf++)
#pragma unroll
            for (int nf = 0; nf < 4; nf++) {
                hmma(acc[mf][nf], ah[mf], bh[nf]);
                hmma(acc[mf][nf], ah[mf], bl[nf]);
                hmma(acc[mf][nf], al[mf], bh[nf]);
            }
    };

    // ---- pipeline: 4-stage ring, prefetch distance 2, one sync/stage ----
    cp_stage(0); CP_COMMIT();
    cp_stage(1); CP_COMMIT();
    ldgB(0);
    for (int s = 0; s < S; s++) {
        stsB(s);
        ldgB(s + 1);
        if (s + 2 < S) { cp_stage(s + 2); CP_COMMIT(); CP_WAIT(2); }
        else if (s + 1 < S) { CP_WAIT(1); }
        else { CP_WAIT(0); }
        __syncthreads();
        compute(s & 3);
    }

    // ---- epilogue ----
    const int g8 = lane >> 2, tg = lane & 3;
    float pm = -1e30f, ps = 0.f;   // mode1 fused softmax partial
#pragma unroll
    for (int mf = 0; mf < 4; mf++)
#pragma unroll
        for (int nf = 0; nf < 4; nf++) {
            int r0 = wm + mf * 16 + g8, cc = wn + nf * 8 + tg * 2;
#pragma unroll
            for (int h = 0; h < 2; h++) {
                int row = r0 + h * 8;
                float f0 = acc[mf][nf][h * 2], f1 = acc[mf][nf][h * 2 + 1];
                if (MODE == 0) {
                    size_t o = ((size_t)n * 768 + m0 + row) * LDIM + j0 + cc;
                    wrpair(g_tpg_hi + o, g_tpg_lo + o, f0, f1);
                } else if (MODE == 1) {
                    *(float2*)(cbuf + ((size_t)n * LDIM + m0 + row) * LDIM + j0 + cc) =
                        make_float2(f0, f1);
                    float vm = fmaxf(f0, f1);
                    if (vm > pm) { ps *= __expf(pm - vm); pm = vm; }
                    ps += __expf(f0 - pm) + __expf(f1 - pm);
                } else if (MODE == 2) {
                    f0 *= iZ; f1 *= iZ;
                    size_t o = ((size_t)n * CDIM + m0 + row) * LDIM + j0 + cc;
                    wrpair(g_at_hi + o, g_at_lo + o, f0, f1);
                } else {
                    const float2 xv = *(const float2*)(x + ((size_t)n * CDIM + m0 + row) * LDIM + j0 + cc);
                    *(float2*)(ybuf + ((size_t)n * CDIM + m0 + row) * LDIM + j0 + cc) =
                        make_float2(f0 + xv.x, f1 + xv.y);
                }
            }
        }

    if (MODE == 1) {
        // block-reduce (pm, ps) over 256 threads; reuse ring smem
        __syncthreads();
        float* rm = (float*)smbuf;
        float* rs = rm + 256;
        rm[tid] = pm; rs[tid] = ps;
        __syncthreads();
        for (int str = 128; str > 0; str >>= 1) {
            if (tid < str) {
                float m2 = rm[tid + str], s2 = rs[tid + str];
                float M = fmaxf(rm[tid], m2);
                rs[tid] = rs[tid] * __expf(rm[tid] - M) + s2 * __expf(m2 - M);
                rm[tid] = M;
            }
            __syncthreads();
        }
        if (tid == 0) {
            int blk = blockIdx.y * 8 + blockIdx.x;
            g_partm[n * 64 + blk] = rm[0];
            g_parts[n * 64 + blk] = rs[0];
        }
    }
}

// ---------------- softmax final combine ----------------
__global__ __launch_bounds__(64) void k_sm_final() {
    __shared__ float rm[64], rs[64];
    const int n = blockIdx.x, tid = threadIdx.x;
    float m = g_partm[n * 64 + tid];
    rm[tid] = m;
    __syncthreads();
    for (int s = 32; s > 0; s >>= 1) {
        if (tid < s) rm[tid] = fmaxf(rm[tid], rm[tid + s]);
        __syncthreads();
    }
    const float M = rm[0];
    __syncthreads();
    rs[tid] = g_parts[n * 64 + tid] * __expf(m - M);
    __syncthreads();
    for (int s = 32; s > 0; s >>= 1) {
        if (tid < s) rs[tid] += rs[tid + s];
        __syncthreads();
    }
    if (tid == 0) { g_M[n] = M; g_invZ[n] = 1.f / rs[0]; }
}

// =====================================================================
extern "C" void kernel_launch(void* const* d_in, const int* in_sizes, int n_in,
                              void* d_out, int out_size) {
    const float* x  = (const float*)d_in[0];
    const float* wt = (const float*)d_in[1];
    const float* wp = (const float*)d_in[2];
    const float* wg = (const float*)d_in[3];
    const float* wr = (const float*)d_in[4];
    float* out = (float*)d_out;
    float* c_out = out;                              // [16,1024,1024]
    float* y_out = out + (size_t)NB * LDIM * LDIM;   // [16,256,32,32]

    constexpr int SM_A = 4 * (2 * 128 * 24 + 2 * 16 * 136) * 2;   // 83968 B
    constexpr int SM_T = 4 * (2 * 16 * 136 + 2 * 16 * 136) * 2;   // 69632 B
    cudaFuncSetAttribute(gemm_mma<0>, cudaFuncAttributeMaxDynamicSharedMemorySize, SM_A);
    cudaFuncSetAttribute(gemm_mma<1>, cudaFuncAttributeMaxDynamicSharedMemorySize, SM_T);
    cudaFuncSetAttribute(gemm_mma<2>, cudaFuncAttributeMaxDynamicSharedMemorySize, SM_A);
    cudaFuncSetAttribute(gemm_mma<3>, cudaFuncAttributeMaxDynamicSharedMemorySize, SM_A);

    k_cvt_w<<<256, 256>>>(wt, wp, wg, wr);
    k_cvt_x<<<4096, 256>>>(x);
    gemm_mma<0><<<dim3(8, 6, NB), 256, SM_A>>>(x, c_out, y_out);
    gemm_mma<1><<<dim3(8, 8, NB), 256, SM_T>>>(x, c_out, y_out);
    k_sm_final<<<NB, 64>>>();
    gemm_mma<2><<<dim3(8, 2, NB), 256, SM_A>>>(x, c_out, y_out);
    gemm_mma<3><<<dim3(8, 2, NB), 256, SM_A>>>(x, c_out, y_out);
}

// round 15
// speedup vs baseline: 2.9450x; 1.0280x over previous
#include <cuda_runtime.h>
#include <cuda_bf16.h>
#include <stdint.h>
#include <math.h>

#define LDIM 1024
#define CDIM 256
#define NB   16

// ---------------- scratch (device globals) ----------------
__device__ uint16_t g_w_hi[768 * 256], g_w_lo[768 * 256];   // wt, wp, W2 stacked
__device__ float    g_w2f[256 * 256];                        // W2 = wr @ wg (fp32)
__device__ uint16_t g_x_hi[16ull * 256 * 1024], g_x_lo[16ull * 256 * 1024];
__device__ uint16_t g_tpg_hi[3ull * 16 * 256 * 1024], g_tpg_lo[3ull * 16 * 256 * 1024];
__device__ float g_partm[16 * 64], g_parts[16 * 64], g_M[16], g_invZ[16];

// ---------------- helpers ----------------
__device__ __forceinline__ uint32_t smem_u32(const void* p) {
    uint32_t a;
    asm("{ .reg .u64 t; cvta.to.shared.u64 t, %1; cvt.u32.u64 %0, t; }" : "=r"(a) : "l"(p));
    return a;
}
__device__ __forceinline__ void hmma(float* c, const uint32_t* a, const uint32_t* b) {
    asm volatile(
        "mma.sync.aligned.m16n8k16.row.col.f32.bf16.bf16.f32 "
        "{%0,%1,%2,%3}, {%4,%5,%6,%7}, {%8,%9}, {%0,%1,%2,%3};"
        : "+f"(c[0]), "+f"(c[1]), "+f"(c[2]), "+f"(c[3])
        : "r"(a[0]), "r"(a[1]), "r"(a[2]), "r"(a[3]), "r"(b[0]), "r"(b[1]));
}
__device__ __forceinline__ void ldsm4(uint32_t* r, uint32_t addr) {
    asm volatile("ldmatrix.sync.aligned.m8n8.x4.shared.b16 {%0,%1,%2,%3}, [%4];"
                 : "=r"(r[0]), "=r"(r[1]), "=r"(r[2]), "=r"(r[3]) : "r"(addr));
}
__device__ __forceinline__ void ldsm4t(uint32_t* r, uint32_t addr) {
    asm volatile("ldmatrix.sync.aligned.m8n8.x4.trans.shared.b16 {%0,%1,%2,%3}, [%4];"
                 : "=r"(r[0]), "=r"(r[1]), "=r"(r[2]), "=r"(r[3]) : "r"(addr));
}
__device__ __forceinline__ void cp16(uint32_t daddr, const void* src) {
    asm volatile("cp.async.cg.shared.global [%0], [%1], 16;" ::"r"(daddr), "l"(src) : "memory");
}
#define CP_COMMIT() asm volatile("cp.async.commit_group;" ::: "memory")
#define CP_WAIT(n)  asm volatile("cp.async.wait_group %0;" ::"n"(n) : "memory")

__device__ __forceinline__ uint32_t pk2(float a, float b) {
    __nv_bfloat162 t = __floats2bfloat162_rn(a, b);
    return reinterpret_cast<uint32_t&>(t);
}
__device__ __forceinline__ void wrpair(uint16_t* hi, uint16_t* lo, float a, float b) {
    float ha = __bfloat162float(__float2bfloat16(a));
    float hb = __bfloat162float(__float2bfloat16(b));
    *(uint32_t*)hi = pk2(a, b);
    *(uint32_t*)lo = pk2(a - ha, b - hb);
}

// ---------------- W2 = wr @ wg (fp32, tiny) ----------------
__global__ __launch_bounds__(256) void k_w2(const float* __restrict__ wr,
                                            const float* __restrict__ wg) {
    __shared__ float wrow[256];
    const int c = blockIdx.x, i = threadIdx.x;
    wrow[i] = wr[c * 256 + i];
    __syncthreads();
    float s = 0.f;
#pragma unroll 8
    for (int a = 0; a < 256; a++) s = fmaf(wrow[a], wg[a * 256 + i], s);
    g_w2f[c * 256 + i] = s;
}

// ---------------- conversion passes ----------------
__global__ __launch_bounds__(256) void k_cvt_w(const float* __restrict__ wt,
                                               const float* __restrict__ wp) {
    int idx = blockIdx.x * 256 + threadIdx.x;   // 192 blocks: 768*256/4 chunks
    int e = idx * 4, row = e >> 8, col = e & 255;
    const float* s = (row < 256) ? wt + (size_t)row * 256
                   : (row < 512) ? wp + (size_t)(row - 256) * 256
                                 : g_w2f + (size_t)(row - 512) * 256;
    float4 v = *(const float4*)(s + col);
    size_t o = (size_t)row * 256 + col;
    wrpair(g_w_hi + o, g_w_lo + o, v.x, v.y);
    wrpair(g_w_hi + o + 2, g_w_lo + o + 2, v.z, v.w);
}
__global__ __launch_bounds__(256) void k_cvt_x(const float* __restrict__ x) {
    size_t idx = (size_t)blockIdx.x * 256 + threadIdx.x;
    float4 v = ((const float4*)x)[idx];
    size_t o = idx * 4;
    wrpair(g_x_hi + o, g_x_lo + o, v.x, v.y);
    wrpair(g_x_hi + o + 2, g_x_lo + o + 2, v.z, v.w);
}

// =====================================================================
// Pipelined mma.sync GEMM: 128x128 block, BK=16, 4-stage ring, one sync
// per stage, 2 CTAs/SM. 8 warps (64x32 warp tile), bf16 hi/lo 3-term split.
// MODE: 0=t,p,G2   1=c (A = t via ldmatrix.trans, fused softmax partial)
//       2=y = x + iZ * (G2 @ exp(c - M))   (exp fused, residual fused)
// =====================================================================
template <int MODE>
__global__ __launch_bounds__(256, 2) void gemm_mma(const float* __restrict__ x,
                                                   float* __restrict__ cbuf,
                                                   float* __restrict__ ybuf) {
    constexpr int S     = (MODE == 2) ? 64 : 16;               // K/16 stages
    constexpr int APL   = (MODE == 1) ? 16 * 136 : 128 * 24;   // A plane elems
    constexpr int BPL   = 16 * 136;
    constexpr int STAGE = 2 * APL + 2 * BPL;
    extern __shared__ __align__(16) uint16_t smbuf[];

    const int tid = threadIdx.x, lane = tid & 31, wid = tid >> 5;
    const int n = blockIdx.z, j0 = blockIdx.x * 128, m0 = blockIdx.y * 128;
    const int wm = (wid & 1) * 64, wn = (wid >> 1) * 32;

    const uint16_t *Aph, *Apl, *Bph = nullptr, *Bpl = nullptr;
    const float* Bf = nullptr;
    float eM = 0.f, iZ = 1.f;
    size_t AKW = 256;
    if (MODE == 0) {
        Aph = g_w_hi + (size_t)m0 * 256;  Apl = g_w_lo + (size_t)m0 * 256;
        Bph = g_x_hi + (size_t)n * CDIM * LDIM;  Bpl = g_x_lo + (size_t)n * CDIM * LDIM;
    } else if (MODE == 1) {
        Aph = g_tpg_hi + (size_t)n * 768 * LDIM;  Apl = g_tpg_lo + (size_t)n * 768 * LDIM;
        Bph = g_tpg_hi + ((size_t)n * 768 + 256) * LDIM;
        Bpl = g_tpg_lo + ((size_t)n * 768 + 256) * LDIM;
    } else {
        Aph = g_tpg_hi + ((size_t)n * 768 + 512 + m0) * LDIM;
        Apl = g_tpg_lo + ((size_t)n * 768 + 512 + m0) * LDIM;
        AKW = 1024;
        Bf = cbuf + (size_t)n * LDIM * LDIM;
        eM = g_M[n]; iZ = g_invZ[n];
    }

    float acc[4][4][4];
#pragma unroll
    for (int a = 0; a < 4; a++)
#pragma unroll
        for (int b = 0; b < 4; b++)
#pragma unroll
            for (int c = 0; c < 4; c++) acc[a][b][c] = 0.f;

    float4 vB[2];   // mode2 B register staging (16x128 fp32 / 256 thr)

    auto cp_stage = [&](int s) {
        const int k0 = s * 16;
        uint16_t* st = smbuf + (size_t)(s & 3) * STAGE;
        uint16_t* Ah = st;            uint16_t* Al = st + APL;
        uint16_t* Bh = st + 2 * APL;  uint16_t* Bl = st + 2 * APL + BPL;
        if (MODE == 1) {
            int row = tid >> 4, seg = (tid & 15) * 8;
            size_t so = (size_t)(k0 + row) * LDIM + m0 + seg;
            cp16(smem_u32(Ah + row * 136 + seg), Aph + so);
            cp16(smem_u32(Al + row * 136 + seg), Apl + so);
        } else {
            int m = tid >> 1, kseg = (tid & 1) * 8;
            size_t so = (size_t)m * AKW + k0 + kseg;
            cp16(smem_u32(Ah + m * 24 + kseg), Aph + so);
            cp16(smem_u32(Al + m * 24 + kseg), Apl + so);
        }
        if (MODE != 2) {
            int row = tid >> 4, seg = (tid & 15) * 8;
            size_t so = (size_t)(k0 + row) * LDIM + j0 + seg;
            cp16(smem_u32(Bh + row * 136 + seg), Bph + so);
            cp16(smem_u32(Bl + row * 136 + seg), Bpl + so);
        }
    };
    auto ldgB = [&](int s) {
        if (MODE == 2 && s < S) {
            const int k0 = s * 16;
#pragma unroll
            for (int u = 0; u < 2; u++) {
                int vi = tid + 256 * u, k = vi >> 5, j4 = (vi & 31) * 4;
                vB[u] = *(const float4*)(Bf + (size_t)(k0 + k) * LDIM + j0 + j4);
            }
        }
    };
    auto stsB = [&](int s) {
        if (MODE == 2) {
            uint16_t* st = smbuf + (size_t)(s & 3) * STAGE;
            uint16_t* Bh = st + 2 * APL;  uint16_t* Bl = st + 2 * APL + BPL;
#pragma unroll
            for (int u = 0; u < 2; u++) {
                int vi = tid + 256 * u, k = vi >> 5, j4 = (vi & 31) * 4;
                float e0 = __expf(vB[u].x - eM), e1 = __expf(vB[u].y - eM);
                float e2 = __expf(vB[u].z - eM), e3 = __expf(vB[u].w - eM);
                wrpair(Bh + k * 136 + j4,     Bl + k * 136 + j4,     e0, e1);
                wrpair(Bh + k * 136 + j4 + 2, Bl + k * 136 + j4 + 2, e2, e3);
            }
        }
    };

    // lane-constant ldmatrix offsets
    const int amr = lane & 15, akc = (lane >> 4) * 8;                 // A non-trans
    const int tkr = (lane & 7) + ((lane >> 4) << 3);                  // A trans k-row
    const int tmc = ((lane >> 3) & 1) * 8;                            // A trans m-col
    const int bkr = lane & 15, bnc = (lane >> 4) * 8;                 // B

    auto compute = [&](int buf) {
        uint16_t* st = smbuf + (size_t)buf * STAGE;
        uint32_t abh = smem_u32(st),            abl = smem_u32(st + APL);
        uint32_t bbh = smem_u32(st + 2 * APL),  bbl = smem_u32(st + 2 * APL + BPL);
        uint32_t ah[4][4], al[4][4], bh[4][2], bl[4][2];
#pragma unroll
        for (int mf = 0; mf < 4; mf++) {
            if (MODE == 1) {
                uint32_t off = (uint32_t)(tkr * 136 + wm + mf * 16 + tmc) * 2;
                ldsm4t(ah[mf], abh + off);
                ldsm4t(al[mf], abl + off);
            } else {
                uint32_t off = (uint32_t)((wm + mf * 16 + amr) * 24 + akc) * 2;
                ldsm4(ah[mf], abh + off);
                ldsm4(al[mf], abl + off);
            }
        }
#pragma unroll
        for (int nq = 0; nq < 2; nq++) {
            uint32_t off = (uint32_t)(bkr * 136 + wn + nq * 16 + bnc) * 2;
            uint32_t r[4];
            ldsm4t(r, bbh + off);
            bh[nq * 2][0] = r[0]; bh[nq * 2][1] = r[1];
            bh[nq * 2 + 1][0] = r[2]; bh[nq * 2 + 1][1] = r[3];
            ldsm4t(r, bbl + off);
            bl[nq * 2][0] = r[0]; bl[nq * 2][1] = r[1];
            bl[nq * 2 + 1][0] = r[2]; bl[nq * 2 + 1][1] = r[3];
        }
#pragma unroll
        for (int mf = 0; mf < 4; mf++)
#pragma unroll
            for (int nf = 0; nf < 4; nf++) {
                hmma(acc[mf][nf], ah[mf], bh[nf]);
                hmma(acc[mf][nf], ah[mf], bl[nf]);
                hmma(acc[mf][nf], al[mf], bh[nf]);
            }
    };

    // ---- pipeline: 4-stage ring, prefetch distance 2, one sync/stage ----
    cp_stage(0); CP_COMMIT();
    cp_stage(1); CP_COMMIT();
    ldgB(0);
    for (int s = 0; s < S; s++) {
        stsB(s);
        ldgB(s + 1);
        if (s + 2 < S) { cp_stage(s + 2); CP_COMMIT(); CP_WAIT(2); }
        else if (s + 1 < S) { CP_WAIT(1); }
        else { CP_WAIT(0); }
        __syncthreads();
        compute(s & 3);
    }

    // ---- epilogue ----
    const int g8 = lane >> 2, tg = lane & 3;
    float pm = -1e30f, ps = 0.f;   // mode1 fused softmax partial
#pragma unroll
    for (int mf = 0; mf < 4; mf++)
#pragma unroll
        for (int nf = 0; nf < 4; nf++) {
            int r0 = wm + mf * 16 + g8, cc = wn + nf * 8 + tg * 2;
#pragma unroll
            for (int h = 0; h < 2; h++) {
                int row = r0 + h * 8;
                float f0 = acc[mf][nf][h * 2], f1 = acc[mf][nf][h * 2 + 1];
                if (MODE == 0) {
                    size_t o = ((size_t)n * 768 + m0 + row) * LDIM + j0 + cc;
                    wrpair(g_tpg_hi + o, g_tpg_lo + o, f0, f1);
                } else if (MODE == 1) {
                    *(float2*)(cbuf + ((size_t)n * LDIM + m0 + row) * LDIM + j0 + cc) =
                        make_float2(f0, f1);
                    float vm = fmaxf(f0, f1);
                    if (vm > pm) { ps *= __expf(pm - vm); pm = vm; }
                    ps += __expf(f0 - pm) + __expf(f1 - pm);
                } else {
                    const float2 xv = *(const float2*)(x + ((size_t)n * CDIM + m0 + row) * LDIM + j0 + cc);
                    *(float2*)(ybuf + ((size_t)n * CDIM + m0 + row) * LDIM + j0 + cc) =
                        make_float2(f0 * iZ + xv.x, f1 * iZ + xv.y);
                }
            }
        }

    if (MODE == 1) {
        // block-reduce (pm, ps) over 256 threads; reuse ring smem
        __syncthreads();
        float* rm = (float*)smbuf;
        float* rs = rm + 256;
        rm[tid] = pm; rs[tid] = ps;
        __syncthreads();
        for (int str = 128; str > 0; str >>= 1) {
            if (tid < str) {
                float m2 = rm[tid + str], s2 = rs[tid + str];
                float M = fmaxf(rm[tid], m2);
                rs[tid] = rs[tid] * __expf(rm[tid] - M) + s2 * __expf(m2 - M);
                rm[tid] = M;
            }
            __syncthreads();
        }
        if (tid == 0) {
            int blk = blockIdx.y * 8 + blockIdx.x;
            g_partm[n * 64 + blk] = rm[0];
            g_parts[n * 64 + blk] = rs[0];
        }
    }
}

// ---------------- softmax final combine ----------------
__global__ __launch_bounds__(64) void k_sm_final() {
    __shared__ float rm[64], rs[64];
    const int n = blockIdx.x, tid = threadIdx.x;
    float m = g_partm[n * 64 + tid];
    rm[tid] = m;
    __syncthreads();
    for (int s = 32; s > 0; s >>= 1) {
        if (tid < s) rm[tid] = fmaxf(rm[tid], rm[tid + s]);
        __syncthreads();
    }
    const float M = rm[0];
    __syncthreads();
    rs[tid] = g_parts[n * 64 + tid] * __expf(m - M);
    __syncthreads();
    for (int s = 32; s > 0; s >>= 1) {
        if (tid < s) rs[tid] += rs[tid + s];
        __syncthreads();
    }
    if (tid == 0) { g_M[n] = M; g_invZ[n] = 1.f / rs[0]; }
}

// =====================================================================
extern "C" void kernel_launch(void* const* d_in, const int* in_sizes, int n_in,
                              void* d_out, int out_size) {
    const float* x  = (const float*)d_in[0];
    const float* wt = (const float*)d_in[1];
    const float* wp = (const float*)d_in[2];
    const float* wg = (const float*)d_in[3];
    const float* wr = (const float*)d_in[4];
    float* out = (float*)d_out;
    float* c_out = out;                              // [16,1024,1024]
    float* y_out = out + (size_t)NB * LDIM * LDIM;   // [16,256,32,32]

    constexpr int SM_A = 4 * (2 * 128 * 24 + 2 * 16 * 136) * 2;   // 83968 B
    constexpr int SM_T = 4 * (2 * 16 * 136 + 2 * 16 * 136) * 2;   // 69632 B
    cudaFuncSetAttribute(gemm_mma<0>, cudaFuncAttributeMaxDynamicSharedMemorySize, SM_A);
    cudaFuncSetAttribute(gemm_mma<1>, cudaFuncAttributeMaxDynamicSharedMemorySize, SM_T);
    cudaFuncSetAttribute(gemm_mma<2>, cudaFuncAttributeMaxDynamicSharedMemorySize, SM_A);

    k_w2<<<256, 256>>>(wr, wg);                      // W2 = wr @ wg (fp32)
    k_cvt_w<<<192, 256>>>(wt, wp);                   // planes: wt, wp, W2
    k_cvt_x<<<4096, 256>>>(x);
    gemm_mma<0><<<dim3(8, 6, NB), 256, SM_A>>>(x, c_out, y_out);   // t, p, G2
    gemm_mma<1><<<dim3(8, 8, NB), 256, SM_T>>>(x, c_out, y_out);   // c + partials
    k_sm_final<<<NB, 64>>>();
    gemm_mma<2><<<dim3(8, 2, NB), 256, SM_A>>>(x, c_out, y_out);   // y direct
}